// round 14
// baseline (speedup 1.0000x reference)
#include <cuda_runtime.h>
#include <math.h>
#include <math_constants.h>

#define NB   4
#define NPTS 8192
#define BN   (NB*NPTS)   // 32768
#define D    128
#define KNN  16
#define G    16
#define NCELLS (G*G*G)   // 4096 cells per batch
#define TPW  128         // tile slots per warp
#define NTILES (NPTS/TPW) // 64 tiles per batch
#define NW   4           // warps per query group

// ---------------- scratch (static device allocations) ----------------
__device__ float4   g_xyzw[BN];        // (-2x,-2y,-2z, |x|^2) per point (orig order)
__device__ float4   g_spts[BN];        // same, sorted by (batch, morton cell)
__device__ int      g_sidx[BN];        // sorted slot -> original local idx
__device__ unsigned g_cnt[NB*NCELLS];  // histogram
__device__ unsigned g_off[NB*NCELLS];  // cell start offsets (batch-local)
__device__ unsigned g_cur[NB*NCELLS];  // scatter cursors
__device__ unsigned g_bblo[NB*3], g_bbhi[NB*3];  // encoded bbox
__device__ float4   g_tlo[NB*NTILES];  // per-tile AABB min (xyz)
__device__ float4   g_thi[NB*NTILES];  // per-tile AABB max (xyz)
__device__ float  g_ksum[BN];          // feat . rowsum(Wk)
__device__ int    g_idx[BN*KNN];       // knn indices (within batch)
__device__ float  g_v[BN*D];           // feat @ Wv + bv
__device__ float  g_hbar[BN*D];        // sum_k attn_k * h_k
__device__ float  g_vbar[BN*D];        // sum_k attn_k * v_k
__device__ float  g_wkrs[D];           // rowsum over out-dim of Wk
__device__ float  g_wp2rs[D];          // rowsum over out-dim of Wp2
__device__ float  g_cvec[D];           // bp2 @ Wo + bo
__device__ float  g_wf[D*D];           // Wp2 @ Wo

// ---------------- helpers ----------------
__device__ __forceinline__ unsigned fenc(float f) {
    unsigned u = __float_as_uint(f);
    return (u & 0x80000000u) ? ~u : (u | 0x80000000u);
}
__device__ __forceinline__ float fdec(unsigned u) {
    return (u & 0x80000000u) ? __uint_as_float(u ^ 0x80000000u) : __uint_as_float(~u);
}
__device__ __forceinline__ unsigned msp4(unsigned x) {
    return (x & 1u) | ((x & 2u) << 2) | ((x & 4u) << 4) | ((x & 8u) << 6);
}
__device__ __forceinline__ unsigned morton3(int cx, int cy, int cz) {
    return msp4((unsigned)cx) | (msp4((unsigned)cy) << 1) | (msp4((unsigned)cz) << 2);
}
__device__ __forceinline__ int cell1(float x, float lo, float inv) {
    int v = (int)((x - lo) * inv);
    return v < 0 ? 0 : (v > G-1 ? G-1 : v);
}

// ---------------- init ----------------
__global__ void k_zero() {   // 64 blocks x 256
    int i = blockIdx.x*256 + threadIdx.x;
    g_cnt[i] = 0;
    if (i < NB*3) { g_bblo[i] = 0xFFFFFFFFu; g_bbhi[i] = 0u; }
}

// ---------------- weight prep ----------------
__global__ void k_weights(const float* __restrict__ Wk, const float* __restrict__ Wp2,
                          const float* __restrict__ bp2, const float* __restrict__ Wo,
                          const float* __restrict__ bo) {
    int i = threadIdx.x;
    float a = 0.f, b = 0.f, c = bo[i];
    for (int j = 0; j < D; ++j) { a += Wk[i*D + j]; b += Wp2[i*D + j]; }
    for (int k = 0; k < D; ++k) c = fmaf(bp2[k], Wo[k*D + i], c);
    g_wkrs[i] = a; g_wp2rs[i] = b; g_cvec[i] = c;
}

__global__ void k_wfused(const float* __restrict__ Wp2, const float* __restrict__ Wo) {
    int d = threadIdx.x & (D-1);
    int i = blockIdx.x*2 + (threadIdx.x >> 7);
    float a = 0.f;
    for (int k = 0; k < D; ++k) a = fmaf(Wp2[i*D + k], Wo[k*D + d], a);
    g_wf[i*D + d] = a;
}

// ---------------- per-point prep: xyzw + ksum ----------------
__global__ void k_prep(const float* __restrict__ xyz, const float* __restrict__ feat) {
    int warp = threadIdx.x >> 5, lane = threadIdx.x & 31;
    int p = blockIdx.x*8 + warp;
    const float* fr = feat + (size_t)p*D;
    float acc = 0.f;
    #pragma unroll
    for (int i = 0; i < 4; ++i) {
        int d = lane + 32*i;
        acc = fmaf(fr[d], g_wkrs[d], acc);
    }
    #pragma unroll
    for (int off = 16; off; off >>= 1) acc += __shfl_xor_sync(0xffffffffu, acc, off);
    if (lane == 0) {
        g_ksum[p] = acc;
        float x = xyz[3*p], y = xyz[3*p+1], z = xyz[3*p+2];
        g_xyzw[p] = make_float4(-2.f*x, -2.f*y, -2.f*z, x*x + y*y + z*z);
    }
}

// ---------------- bbox per batch (3 dims) ----------------
__global__ void k_bbox(const float* __restrict__ xyz) {   // grid (32, NB), block 256
    int b = blockIdx.y;
    __shared__ unsigned slo[3], shi[3];
    if (threadIdx.x < 3) { slo[threadIdx.x] = 0xFFFFFFFFu; shi[threadIdx.x] = 0u; }
    __syncthreads();
    int p = blockIdx.x*256 + threadIdx.x;
    if (p < NPTS) {
        const float* r = xyz + (size_t)(b*NPTS + p)*3;
        #pragma unroll
        for (int a = 0; a < 3; ++a) {
            unsigned e = fenc(r[a]);
            atomicMin(&slo[a], e); atomicMax(&shi[a], e);
        }
    }
    __syncthreads();
    if (threadIdx.x < 3) {
        atomicMin(&g_bblo[b*3 + threadIdx.x], slo[threadIdx.x]);
        atomicMax(&g_bbhi[b*3 + threadIdx.x], shi[threadIdx.x]);
    }
}

// ---------------- histogram over morton cells ----------------
__global__ void k_hist(const float* __restrict__ xyz) {
    int i = blockIdx.x*256 + threadIdx.x;
    int b = i >> 13;
    float lox = fdec(g_bblo[b*3]),   loy = fdec(g_bblo[b*3+1]), loz = fdec(g_bblo[b*3+2]);
    float ivx = (float)G/(fdec(g_bbhi[b*3])   - lox + 1e-4f);
    float ivy = (float)G/(fdec(g_bbhi[b*3+1]) - loy + 1e-4f);
    float ivz = (float)G/(fdec(g_bbhi[b*3+2]) - loz + 1e-4f);
    float x = xyz[3*i], y = xyz[3*i+1], z = xyz[3*i+2];
    unsigned m = morton3(cell1(x,lox,ivx), cell1(y,loy,ivy), cell1(z,loz,ivz));
    atomicAdd(&g_cnt[b*NCELLS + m], 1u);
}

// ---------------- exclusive scan per batch (4096 cells) ----------------
__global__ void k_scan() {   // grid NB, block 1024
    int b = blockIdx.x;
    int tid = threadIdx.x, lane = tid & 31, wid = tid >> 5;
    __shared__ unsigned ws[32];
    __shared__ unsigned carry_s;
    if (tid == 0) carry_s = 0;
    __syncthreads();
    for (int it = 0; it < NCELLS/1024; ++it) {
        unsigned carry = carry_s;
        int i = b*NCELLS + it*1024 + tid;
        unsigned v = g_cnt[i];
        unsigned s = v;
        #pragma unroll
        for (int off = 1; off < 32; off <<= 1) {
            unsigned n = __shfl_up_sync(0xffffffffu, s, off);
            if (lane >= off) s += n;
        }
        if (lane == 31) ws[wid] = s;
        __syncthreads();
        if (wid == 0) {
            unsigned t = ws[lane];
            #pragma unroll
            for (int off = 1; off < 32; off <<= 1) {
                unsigned n = __shfl_up_sync(0xffffffffu, t, off);
                if (lane >= off) t += n;
            }
            ws[lane] = t;
        }
        __syncthreads();
        unsigned excl = s - v + (wid ? ws[wid-1] : 0u) + carry;
        g_off[i] = excl; g_cur[i] = excl;
        __syncthreads();
        if (tid == 1023) carry_s = excl + v;
        __syncthreads();
    }
}

// ---------------- scatter into morton-sorted order ----------------
__global__ void k_scatter(const float* __restrict__ xyz) {
    int i = blockIdx.x*256 + threadIdx.x;
    int b = i >> 13;
    float lox = fdec(g_bblo[b*3]),   loy = fdec(g_bblo[b*3+1]), loz = fdec(g_bblo[b*3+2]);
    float ivx = (float)G/(fdec(g_bbhi[b*3])   - lox + 1e-4f);
    float ivy = (float)G/(fdec(g_bbhi[b*3+1]) - loy + 1e-4f);
    float ivz = (float)G/(fdec(g_bbhi[b*3+2]) - loz + 1e-4f);
    float x = xyz[3*i], y = xyz[3*i+1], z = xyz[3*i+2];
    unsigned m = morton3(cell1(x,lox,ivx), cell1(y,loy,ivy), cell1(z,loz,ivz));
    unsigned pos = atomicAdd(&g_cur[b*NCELLS + m], 1u);
    int slot = b*NPTS + (int)pos;
    g_spts[slot] = g_xyzw[i];
    g_sidx[slot] = i & (NPTS-1);
}

// ---------------- per-tile AABB (exact, from points) ----------------
__global__ void k_taabb() {   // 32 blocks x 256 (8 warps)
    int w = threadIdx.x >> 5, lane = threadIdx.x & 31;
    int tile = blockIdx.x*8 + w;
    float xmn = CUDART_INF_F, ymn = CUDART_INF_F, zmn = CUDART_INF_F;
    float xmx = -CUDART_INF_F, ymx = -CUDART_INF_F, zmx = -CUDART_INF_F;
    #pragma unroll
    for (int i = 0; i < TPW/32; ++i) {
        float4 c = g_spts[tile*TPW + lane + i*32];
        float x = -0.5f*c.x, y = -0.5f*c.y, z = -0.5f*c.z;
        xmn = fminf(xmn, x); xmx = fmaxf(xmx, x);
        ymn = fminf(ymn, y); ymx = fmaxf(ymx, y);
        zmn = fminf(zmn, z); zmx = fmaxf(zmx, z);
    }
    #pragma unroll
    for (int off = 16; off; off >>= 1) {
        xmn = fminf(xmn, __shfl_xor_sync(0xffffffffu, xmn, off));
        xmx = fmaxf(xmx, __shfl_xor_sync(0xffffffffu, xmx, off));
        ymn = fminf(ymn, __shfl_xor_sync(0xffffffffu, ymn, off));
        ymx = fmaxf(ymx, __shfl_xor_sync(0xffffffffu, ymx, off));
        zmn = fminf(zmn, __shfl_xor_sync(0xffffffffu, zmn, off));
        zmx = fmaxf(zmx, __shfl_xor_sync(0xffffffffu, zmx, off));
    }
    if (lane == 0) {
        g_tlo[tile] = make_float4(xmn, ymn, zmn, 0.f);
        g_thi[tile] = make_float4(xmx, ymx, zmx, 0.f);
    }
}

// ---------------- kNN: AABB-pruned tile scan, replace-max insert ----------------
__global__ void __launch_bounds__(128) k_knn() {
    __shared__ float4 tile_s[NW][TPW];     // 8KB
    __shared__ float  sth[NW][32];         // per-(warp,query) 16th-dist^2
    __shared__ float  md[KNN*NW*32];       // merge keys
    __shared__ int    mi[KNN*NW*32];       // merge slot ids

    int w = threadIdx.x >> 5, lane = threadIdx.x & 31;
    int qslot0 = blockIdx.x*32;            // 32 consecutive morton-sorted queries
    int b = qslot0 >> 13, bbase = b*NPTS;
    int ql = qslot0 & (NPTS-1);
    int slot = qslot0 + lane;
    float4 qc = g_spts[slot];
    float qx = -0.5f*qc.x, qy = -0.5f*qc.y, qz = -0.5f*qc.z, qw = qc.w;

    volatile float* sv = &sth[0][0];
    sth[w][lane] = CUDART_INF_F;

    // UNSORTED top-16 buffer with tracked (max, argmax)
    float kk[KNN]; int ii[KNN];
    #pragma unroll
    for (int s = 0; s < KNN; ++s) { kk[s] = CUDART_INF_F; ii[s] = 0; }
    float thrv = CUDART_INF_F; int thrpos = 0;
    float pkey = 0.f; int psl = 0; bool pval = false;

// replace current max slot with pending, recompute (max, argmax) via tree (depth 4)
#define KNN_FLUSH() do {                                              \
        _Pragma("unroll")                                             \
        for (int s = 0; s < KNN; ++s) {                               \
            bool r_ = (s == thrpos);                                  \
            kk[s] = r_ ? pkey : kk[s];                                \
            ii[s] = r_ ? psl  : ii[s];                                \
        }                                                             \
        float mv[8]; int mp[8];                                       \
        _Pragma("unroll")                                             \
        for (int s = 0; s < 8; ++s) {                                 \
            bool g_ = kk[2*s+1] > kk[2*s];                            \
            mv[s] = g_ ? kk[2*s+1] : kk[2*s];                         \
            mp[s] = g_ ? 2*s+1 : 2*s;                                 \
        }                                                             \
        _Pragma("unroll")                                             \
        for (int h_ = 4; h_ >= 1; h_ >>= 1) {                         \
            _Pragma("unroll")                                         \
            for (int s = 0; s < h_; ++s) {                            \
                bool g_ = mv[s+h_] > mv[s];                           \
                mv[s] = g_ ? mv[s+h_] : mv[s];                        \
                mp[s] = g_ ? mp[s+h_] : mp[s];                        \
            }                                                         \
        }                                                             \
        thrv = mv[0]; thrpos = mp[0];                                 \
    } while (0)

#define SCAN_TILE(T0, CAP) do {                                       \
        __syncwarp();                                                 \
        _Pragma("unroll")                                             \
        for (int i_ = 0; i_ < TPW/32; ++i_)                           \
            tile_s[w][lane + i_*32] = g_spts[bbase + (T0) + lane + i_*32]; \
        __syncwarp();                                                 \
        float thr = fminf(thrv, (CAP));                               \
        _Pragma("unroll 8")                                           \
        for (int j_ = 0; j_ < TPW; ++j_) {                            \
            float4 c = tile_s[w][j_];                                 \
            float key = fmaf(c.x, qx, fmaf(c.y, qy, fmaf(c.z, qz, c.w))); \
            bool hit = key < thr;                                     \
            if (__any_sync(0xffffffffu, hit && pval)) {               \
                if (pval) { KNN_FLUSH(); thr = fminf(thrv, (CAP)); }  \
                pval = false;                                         \
            }                                                         \
            if (hit) { pkey = key; psl = (T0) + j_; pval = true; }    \
        }                                                             \
        if (__any_sync(0xffffffffu, pval)) {                          \
            if (pval) KNN_FLUSH();                                    \
            pval = false;                                             \
        }                                                             \
        sth[w][lane] = thrv + qw;                                     \
    } while (0)

    __syncthreads();
    int tq = ql >> 7;                       // own tile (holds all 32 queries)
    if (w == 0) SCAN_TILE(tq*TPW, CUDART_INF_F);   // warm-start: compact 3D blob
    __syncthreads();

    // each warp handles 16 of the 64 tiles, pruned by exact point-AABB distance
    for (int t = w; t < NTILES; t += NW) {
        if (t == tq) continue;
        float d2s = fminf(fminf(sv[lane], sv[32+lane]), fminf(sv[64+lane], sv[96+lane]));
        d2s = fminf(d2s, thrv + qw);
        float4 blo = g_tlo[b*NTILES + t];
        float4 bhi = g_thi[b*NTILES + t];
        float dx = fmaxf(fmaxf(blo.x - qx, qx - bhi.x), 0.f);
        float dy = fmaxf(fmaxf(blo.y - qy, qy - bhi.y), 0.f);
        float dz = fmaxf(fmaxf(blo.z - qz, qz - bhi.z), 0.f);
        float cd2 = fmaf(dx, dx, fmaf(dy, dy, dz*dz));
        if (__all_sync(0xffffffffu, cd2 >= d2s + 1e-4f)) continue;  // margin > key rounding
        SCAN_TILE(t*TPW, d2s - qw);
    }
#undef SCAN_TILE
#undef KNN_FLUSH

    // ---- sort the unsorted 16-buffer once (bitonic, ascending) ----
#define CSWAPA(a_, b_) do {                                           \
        bool sw_ = kk[a_] > kk[b_];                                   \
        float tv_ = kk[a_]; int ti_ = ii[a_];                         \
        kk[a_] = sw_ ? kk[b_] : kk[a_];  ii[a_] = sw_ ? ii[b_] : ii[a_]; \
        kk[b_] = sw_ ? tv_ : kk[b_];     ii[b_] = sw_ ? ti_ : ii[b_]; \
    } while (0)
    #pragma unroll
    for (int k2 = 2; k2 <= 16; k2 <<= 1) {
        #pragma unroll
        for (int j2 = k2 >> 1; j2 > 0; j2 >>= 1) {
            #pragma unroll
            for (int i2 = 0; i2 < 16; ++i2) {
                int l2 = i2 ^ j2;
                if (l2 > i2) {
                    if ((i2 & k2) == 0) CSWAPA(i2, l2);
                    else                CSWAPA(l2, i2);
                }
            }
        }
    }
#undef CSWAPA

    // ---- 4-way merge of sorted 16-lists (disjoint tiles -> no duplicates) ----
    #pragma unroll
    for (int s = 0; s < KNN; ++s) {
        md[s*(NW*32) + w*32 + lane] = kk[s];
        mi[s*(NW*32) + w*32 + lane] = ii[s];
    }
    __syncthreads();
    if (w == 0) {
        int p0 = 0, p1 = 0, p2 = 0, p3 = 0;
        int oq = g_sidx[slot];
        int* op = g_idx + (size_t)(bbase + oq)*KNN;
        #pragma unroll
        for (int s = 0; s < KNN; ++s) {
            float h0 = md[p0*128 +  0 + lane];
            float h1 = md[p1*128 + 32 + lane];
            float h2 = md[p2*128 + 64 + lane];
            float h3 = md[p3*128 + 96 + lane];
            float best = h0; int bw = 0;
            if (h1 < best) { best = h1; bw = 1; }
            if (h2 < best) { best = h2; bw = 2; }
            if (h3 < best) { best = h3; bw = 3; }
            int pj = (bw == 0) ? p0 : (bw == 1) ? p1 : (bw == 2) ? p2 : p3;
            int sl = mi[pj*128 + bw*32 + lane];
            op[s] = g_sidx[bbase + sl];
            if (bw == 0) ++p0; else if (bw == 1) ++p1; else if (bw == 2) ++p2; else ++p3;
        }
    }
}

// ---------------- v = feat @ Wv + bv ----------------
__global__ void k_gemm_v(const float* __restrict__ feat, const float* __restrict__ Wv,
                         const float* __restrict__ bv) {
    __shared__ float As[16][132];
    __shared__ float Ws[16][132];
    int m0 = blockIdx.x*128;
    int tx = threadIdx.x & 15, ty = threadIdx.x >> 4;
    float acc[8][8];
    #pragma unroll
    for (int i = 0; i < 8; ++i)
        #pragma unroll
        for (int j = 0; j < 8; ++j) acc[i][j] = 0.f;

    for (int kc = 0; kc < D; kc += 16) {
        __syncthreads();
        { int c = threadIdx.x & 3, r = threadIdx.x >> 2;
          #pragma unroll
          for (int rr = 0; rr < 2; ++rr) {
              int mm = r + rr*64;
              float4 v = *(const float4*)&feat[(size_t)(m0+mm)*D + kc + c*4];
              As[c*4+0][mm] = v.x; As[c*4+1][mm] = v.y;
              As[c*4+2][mm] = v.z; As[c*4+3][mm] = v.w;
          }
        }
        { int k = threadIdx.x >> 5, c4 = threadIdx.x & 31;
          #pragma unroll
          for (int kk = 0; kk < 2; ++kk) {
              float4 v = *(const float4*)&Wv[(size_t)(kc + k + kk*8)*D + c4*4];
              Ws[k + kk*8][c4*4+0] = v.x; Ws[k + kk*8][c4*4+1] = v.y;
              Ws[k + kk*8][c4*4+2] = v.z; Ws[k + kk*8][c4*4+3] = v.w;
          }
        }
        __syncthreads();
        #pragma unroll
        for (int k = 0; k < 16; ++k) {
            float a[8], bb[8];
            #pragma unroll
            for (int i = 0; i < 8; ++i) a[i]  = As[k][ty*8 + i];
            #pragma unroll
            for (int j = 0; j < 8; ++j) bb[j] = Ws[k][tx*8 + j];
            #pragma unroll
            for (int i = 0; i < 8; ++i)
                #pragma unroll
                for (int j = 0; j < 8; ++j) acc[i][j] = fmaf(a[i], bb[j], acc[i][j]);
        }
    }
    #pragma unroll
    for (int i = 0; i < 8; ++i) {
        int m = m0 + ty*8 + i;
        #pragma unroll
        for (int j = 0; j < 8; ++j) acc[i][j] += bv[tx*8 + j];
        *(float4*)&g_v[(size_t)m*D + tx*8]     = make_float4(acc[i][0], acc[i][1], acc[i][2], acc[i][3]);
        *(float4*)&g_v[(size_t)m*D + tx*8 + 4] = make_float4(acc[i][4], acc[i][5], acc[i][6], acc[i][7]);
    }
}

// ---------------- fused attention (warp per point) ----------------
__global__ void k_fuse(const float* __restrict__ xyz, const float* __restrict__ Wp1,
                       const float* __restrict__ bp1) {
    __shared__ float sw0[D], sw1[D], sw2[D], sb1[D], srs[D];
    int tid = threadIdx.x;
    sw0[tid] = Wp1[tid]; sw1[tid] = Wp1[D + tid]; sw2[tid] = Wp1[2*D + tid];
    sb1[tid] = bp1[tid]; srs[tid] = g_wp2rs[tid];
    __syncthreads();

    int warp = tid >> 5, lane = tid & 31;
    int p = blockIdx.x*4 + warp;
    int bbase = p & ~(NPTS-1);

    float w0[4], w1[4], w2[4], b1r[4], rs[4];
    #pragma unroll
    for (int i = 0; i < 4; ++i) {
        int d = lane + 32*i;
        w0[i] = sw0[d]; w1[i] = sw1[d]; w2[i] = sw2[d]; b1r[i] = sb1[d]; rs[i] = srs[d];
    }

    float rx = 0.f, ry = 0.f, rz = 0.f, ks = 0.f; int row = 0;
    if (lane < KNN) {
        int nb = g_idx[(size_t)p*KNN + lane];
        row = bbase + nb;
        float qx = xyz[3*p], qy = xyz[3*p+1], qz = xyz[3*p+2];
        rx = qx - xyz[3*row]; ry = qy - xyz[3*row+1]; rz = qz - xyz[3*row+2];
        ks = g_ksum[row];
    }

    float mysc = -CUDART_INF_F;
    #pragma unroll
    for (int k = 0; k < KNN; ++k) {
        float bx = __shfl_sync(0xffffffffu, rx, k);
        float by = __shfl_sync(0xffffffffu, ry, k);
        float bz = __shfl_sync(0xffffffffu, rz, k);
        float part = 0.f;
        #pragma unroll
        for (int i = 0; i < 4; ++i) {
            float h = fmaf(bx, w0[i], fmaf(by, w1[i], fmaf(bz, w2[i], b1r[i])));
            h = fmaxf(h, 0.f);
            part = fmaf(h, rs[i], part);
        }
        #pragma unroll
        for (int off = 16; off; off >>= 1) part += __shfl_xor_sync(0xffffffffu, part, off);
        if (lane == k) mysc = part - ks;
    }
    float mx = mysc;
    #pragma unroll
    for (int off = 16; off; off >>= 1) mx = fmaxf(mx, __shfl_xor_sync(0xffffffffu, mx, off));
    float e = (lane < KNN) ? __expf(mysc - mx) : 0.f;
    float ssum = e;
    #pragma unroll
    for (int off = 16; off; off >>= 1) ssum += __shfl_xor_sync(0xffffffffu, ssum, off);
    float attn = e / ssum;

    float hb[4] = {0,0,0,0}, vb[4] = {0,0,0,0};
    #pragma unroll
    for (int k = 0; k < KNN; ++k) {
        float a  = __shfl_sync(0xffffffffu, attn, k);
        float bx = __shfl_sync(0xffffffffu, rx, k);
        float by = __shfl_sync(0xffffffffu, ry, k);
        float bz = __shfl_sync(0xffffffffu, rz, k);
        int   r  = __shfl_sync(0xffffffffu, row, k);
        const float* vr = g_v + (size_t)r*D;
        #pragma unroll
        for (int i = 0; i < 4; ++i) {
            int d = lane + 32*i;
            float h = fmaf(bx, w0[i], fmaf(by, w1[i], fmaf(bz, w2[i], b1r[i])));
            h = fmaxf(h, 0.f);
            hb[i] = fmaf(a, h, hb[i]);
            vb[i] = fmaf(a, vr[d], vb[i]);
        }
    }
    #pragma unroll
    for (int i = 0; i < 4; ++i) {
        int d = lane + 32*i;
        g_hbar[(size_t)p*D + d] = hb[i];
        g_vbar[(size_t)p*D + d] = vb[i];
    }
}

// ---------------- out = feat + gamma*(vbar@Wo + hbar@Wf + cvec) ----------------
__global__ void k_out(const float* __restrict__ feat, const float* __restrict__ Wo,
                      const float* __restrict__ gamma, float* __restrict__ out) {
    __shared__ float As[16][132];
    __shared__ float Ws[16][132];
    int m0 = blockIdx.x*128;
    int tx = threadIdx.x & 15, ty = threadIdx.x >> 4;
    float acc[8][8];
    #pragma unroll
    for (int i = 0; i < 8; ++i)
        #pragma unroll
        for (int j = 0; j < 8; ++j) acc[i][j] = 0.f;

    for (int ph = 0; ph < 2; ++ph) {
        const float* A = ph ? g_hbar : g_vbar;
        const float* W = ph ? g_wf   : Wo;
        for (int kc = 0; kc < D; kc += 16) {
            __syncthreads();
            { int c = threadIdx.x & 3, r = threadIdx.x >> 2;
              #pragma unroll
              for (int rr = 0; rr < 2; ++rr) {
                  int mm = r + rr*64;
                  float4 v = *(const float4*)&A[(size_t)(m0+mm)*D + kc + c*4];
                  As[c*4+0][mm] = v.x; As[c*4+1][mm] = v.y;
                  As[c*4+2][mm] = v.z; As[c*4+3][mm] = v.w;
              }
            }
            { int k = threadIdx.x >> 5, c4 = threadIdx.x & 31;
              #pragma unroll
              for (int kk = 0; kk < 2; ++kk) {
                  float4 v = *(const float4*)&W[(size_t)(kc + k + kk*8)*D + c4*4];
                  Ws[k + kk*8][c4*4+0] = v.x; Ws[k + kk*8][c4*4+1] = v.y;
                  Ws[k + kk*8][c4*4+2] = v.z; Ws[k + kk*8][c4*4+3] = v.w;
              }
            }
            __syncthreads();
            #pragma unroll
            for (int k = 0; k < 16; ++k) {
                float a[8], bb[8];
                #pragma unroll
                for (int i = 0; i < 8; ++i) a[i]  = As[k][ty*8 + i];
                #pragma unroll
                for (int j = 0; j < 8; ++j) bb[j] = Ws[k][tx*8 + j];
                #pragma unroll
                for (int i = 0; i < 8; ++i)
                    #pragma unroll
                    for (int j = 0; j < 8; ++j) acc[i][j] = fmaf(a[i], bb[j], acc[i][j]);
            }
        }
    }
    float g = *gamma;
    float cv[8];
    #pragma unroll
    for (int j = 0; j < 8; ++j) cv[j] = g_cvec[tx*8 + j];
    #pragma unroll
    for (int i = 0; i < 8; ++i) {
        int m = m0 + ty*8 + i;
        float4 f0 = *(const float4*)&feat[(size_t)m*D + tx*8];
        float4 f1 = *(const float4*)&feat[(size_t)m*D + tx*8 + 4];
        float o0 = f0.x + g*(acc[i][0] + cv[0]);
        float o1 = f0.y + g*(acc[i][1] + cv[1]);
        float o2 = f0.z + g*(acc[i][2] + cv[2]);
        float o3 = f0.w + g*(acc[i][3] + cv[3]);
        float o4 = f1.x + g*(acc[i][4] + cv[4]);
        float o5 = f1.y + g*(acc[i][5] + cv[5]);
        float o6 = f1.z + g*(acc[i][6] + cv[6]);
        float o7 = f1.w + g*(acc[i][7] + cv[7]);
        *(float4*)&out[(size_t)m*D + tx*8]     = make_float4(o0, o1, o2, o3);
        *(float4*)&out[(size_t)m*D + tx*8 + 4] = make_float4(o4, o5, o6, o7);
    }
}

// ---------------- launch ----------------
extern "C" void kernel_launch(void* const* d_in, const int* in_sizes, int n_in,
                              void* d_out, int out_size) {
    const float* xyz  = (const float*)d_in[0];
    const float* feat = (const float*)d_in[1];
    // d_in[2]=Wq, d_in[3]=bq, d_in[5]=bk : mathematically cancel in softmax, unused
    const float* Wk   = (const float*)d_in[4];
    const float* Wv   = (const float*)d_in[6];
    const float* bv   = (const float*)d_in[7];
    const float* Wp1  = (const float*)d_in[8];
    const float* bp1  = (const float*)d_in[9];
    const float* Wp2  = (const float*)d_in[10];
    const float* bp2  = (const float*)d_in[11];
    const float* Wo   = (const float*)d_in[12];
    const float* bo   = (const float*)d_in[13];
    const float* gmm  = (const float*)d_in[14];
    float* out = (float*)d_out;

    k_zero<<<NB*NCELLS/256, 256>>>();
    k_weights<<<1, 128>>>(Wk, Wp2, bp2, Wo, bo);
    k_wfused<<<64, 256>>>(Wp2, Wo);
    k_prep<<<BN/8, 256>>>(xyz, feat);
    k_bbox<<<dim3(32, NB), 256>>>(xyz);
    k_hist<<<BN/256, 256>>>(xyz);
    k_scan<<<NB, 1024>>>();
    k_scatter<<<BN/256, 256>>>(xyz);
    k_taabb<<<NB*NTILES/8, 256>>>();
    k_knn<<<BN/32, 128>>>();
    k_gemm_v<<<BN/128, 256>>>(feat, Wv, bv);
    k_fuse<<<BN/4, 128>>>(xyz, Wp1, bp1);
    k_out<<<BN/128, 256>>>(feat, Wo, gmm, out);
}

// round 15
// speedup vs baseline: 1.3222x; 1.3222x over previous
#include <cuda_runtime.h>
#include <math.h>
#include <math_constants.h>

#define NB   4
#define NPTS 8192
#define BN   (NB*NPTS)   // 32768
#define D    128
#define KNN  16
#define G    16
#define NCELLS (G*G*G)   // 4096 cells per batch
#define TPW  128         // tile slots per warp
#define NTILES (NPTS/TPW) // 64 tiles per batch
#define NW   4           // warps per query group

// ---------------- scratch (static device allocations) ----------------
__device__ float4   g_xyzw[BN];        // (-2x,-2y,-2z, |x|^2) per point (orig order)
__device__ float4   g_spts[BN];        // same, sorted by (batch, morton cell)
__device__ int      g_sidx[BN];        // sorted slot -> original local idx
__device__ unsigned g_cnt[NB*NCELLS];  // histogram
__device__ unsigned g_off[NB*NCELLS];  // cell start offsets (batch-local)
__device__ unsigned g_cur[NB*NCELLS];  // scatter cursors
__device__ unsigned g_bblo[NB*3], g_bbhi[NB*3];  // encoded bbox
__device__ float4   g_tlo[NB*NTILES];  // per-tile AABB min (xyz)
__device__ float4   g_thi[NB*NTILES];  // per-tile AABB max (xyz)
__device__ float  g_ksum[BN];          // feat . rowsum(Wk)
__device__ int    g_idx[BN*KNN];       // knn indices (within batch)
__device__ float  g_hbar[BN*D];        // sum_k attn_k * h_k
__device__ float  g_fbar[BN*D];        // sum_k attn_k * feat_k
__device__ float  g_wkrs[D];           // rowsum over out-dim of Wk
__device__ float  g_wp2rs[D];          // rowsum over out-dim of Wp2
__device__ float  g_cvec[D];           // (bv + bp2) @ Wo + bo
__device__ float  g_wf[D*D];           // Wp2 @ Wo
__device__ float  g_wvo[D*D];          // Wv @ Wo

// ---------------- helpers ----------------
__device__ __forceinline__ unsigned fenc(float f) {
    unsigned u = __float_as_uint(f);
    return (u & 0x80000000u) ? ~u : (u | 0x80000000u);
}
__device__ __forceinline__ float fdec(unsigned u) {
    return (u & 0x80000000u) ? __uint_as_float(u ^ 0x80000000u) : __uint_as_float(~u);
}
__device__ __forceinline__ unsigned msp4(unsigned x) {
    return (x & 1u) | ((x & 2u) << 2) | ((x & 4u) << 4) | ((x & 8u) << 6);
}
__device__ __forceinline__ unsigned morton3(int cx, int cy, int cz) {
    return msp4((unsigned)cx) | (msp4((unsigned)cy) << 1) | (msp4((unsigned)cz) << 2);
}
__device__ __forceinline__ int cell1(float x, float lo, float inv) {
    int v = (int)((x - lo) * inv);
    return v < 0 ? 0 : (v > G-1 ? G-1 : v);
}

// ---------------- init ----------------
__global__ void k_zero() {   // 64 blocks x 256
    int i = blockIdx.x*256 + threadIdx.x;
    g_cnt[i] = 0;
    if (i < NB*3) { g_bblo[i] = 0xFFFFFFFFu; g_bbhi[i] = 0u; }
}

// ---------------- weight prep ----------------
__global__ void k_weights(const float* __restrict__ Wk, const float* __restrict__ Wp2,
                          const float* __restrict__ bp2, const float* __restrict__ Wo,
                          const float* __restrict__ bo, const float* __restrict__ bv) {
    int i = threadIdx.x;
    float a = 0.f, b = 0.f, c = bo[i];
    for (int j = 0; j < D; ++j) { a += Wk[i*D + j]; b += Wp2[i*D + j]; }
    for (int k = 0; k < D; ++k) c = fmaf(bp2[k] + bv[k], Wo[k*D + i], c);
    g_wkrs[i] = a; g_wp2rs[i] = b; g_cvec[i] = c;
}

// Wf = Wp2 @ Wo  and  Wvo = Wv @ Wo   (128 blocks x 256)
__global__ void k_wfused(const float* __restrict__ Wp2, const float* __restrict__ Wv,
                         const float* __restrict__ Wo) {
    int d = threadIdx.x & (D-1);
    int r = blockIdx.x*2 + (threadIdx.x >> 7);   // 0..255
    const float* A = (r < D) ? Wp2 : Wv;
    float* O = (r < D) ? g_wf : g_wvo;
    int i = r & (D-1);
    float a = 0.f;
    for (int k = 0; k < D; ++k) a = fmaf(A[i*D + k], Wo[k*D + d], a);
    O[i*D + d] = a;
}

// ---------------- per-point prep: xyzw + ksum ----------------
__global__ void k_prep(const float* __restrict__ xyz, const float* __restrict__ feat) {
    int warp = threadIdx.x >> 5, lane = threadIdx.x & 31;
    int p = blockIdx.x*8 + warp;
    const float* fr = feat + (size_t)p*D;
    float acc = 0.f;
    #pragma unroll
    for (int i = 0; i < 4; ++i) {
        int d = lane + 32*i;
        acc = fmaf(fr[d], g_wkrs[d], acc);
    }
    #pragma unroll
    for (int off = 16; off; off >>= 1) acc += __shfl_xor_sync(0xffffffffu, acc, off);
    if (lane == 0) {
        g_ksum[p] = acc;
        float x = xyz[3*p], y = xyz[3*p+1], z = xyz[3*p+2];
        g_xyzw[p] = make_float4(-2.f*x, -2.f*y, -2.f*z, x*x + y*y + z*z);
    }
}

// ---------------- bbox per batch (3 dims) ----------------
__global__ void k_bbox(const float* __restrict__ xyz) {   // grid (32, NB), block 256
    int b = blockIdx.y;
    __shared__ unsigned slo[3], shi[3];
    if (threadIdx.x < 3) { slo[threadIdx.x] = 0xFFFFFFFFu; shi[threadIdx.x] = 0u; }
    __syncthreads();
    int p = blockIdx.x*256 + threadIdx.x;
    if (p < NPTS) {
        const float* r = xyz + (size_t)(b*NPTS + p)*3;
        #pragma unroll
        for (int a = 0; a < 3; ++a) {
            unsigned e = fenc(r[a]);
            atomicMin(&slo[a], e); atomicMax(&shi[a], e);
        }
    }
    __syncthreads();
    if (threadIdx.x < 3) {
        atomicMin(&g_bblo[b*3 + threadIdx.x], slo[threadIdx.x]);
        atomicMax(&g_bbhi[b*3 + threadIdx.x], shi[threadIdx.x]);
    }
}

// ---------------- histogram over morton cells ----------------
__global__ void k_hist(const float* __restrict__ xyz) {
    int i = blockIdx.x*256 + threadIdx.x;
    int b = i >> 13;
    float lox = fdec(g_bblo[b*3]),   loy = fdec(g_bblo[b*3+1]), loz = fdec(g_bblo[b*3+2]);
    float ivx = (float)G/(fdec(g_bbhi[b*3])   - lox + 1e-4f);
    float ivy = (float)G/(fdec(g_bbhi[b*3+1]) - loy + 1e-4f);
    float ivz = (float)G/(fdec(g_bbhi[b*3+2]) - loz + 1e-4f);
    float x = xyz[3*i], y = xyz[3*i+1], z = xyz[3*i+2];
    unsigned m = morton3(cell1(x,lox,ivx), cell1(y,loy,ivy), cell1(z,loz,ivz));
    atomicAdd(&g_cnt[b*NCELLS + m], 1u);
}

// ---------------- exclusive scan per batch (4096 cells) ----------------
__global__ void k_scan() {   // grid NB, block 1024
    int b = blockIdx.x;
    int tid = threadIdx.x, lane = tid & 31, wid = tid >> 5;
    __shared__ unsigned ws[32];
    __shared__ unsigned carry_s;
    if (tid == 0) carry_s = 0;
    __syncthreads();
    for (int it = 0; it < NCELLS/1024; ++it) {
        unsigned carry = carry_s;
        int i = b*NCELLS + it*1024 + tid;
        unsigned v = g_cnt[i];
        unsigned s = v;
        #pragma unroll
        for (int off = 1; off < 32; off <<= 1) {
            unsigned n = __shfl_up_sync(0xffffffffu, s, off);
            if (lane >= off) s += n;
        }
        if (lane == 31) ws[wid] = s;
        __syncthreads();
        if (wid == 0) {
            unsigned t = ws[lane];
            #pragma unroll
            for (int off = 1; off < 32; off <<= 1) {
                unsigned n = __shfl_up_sync(0xffffffffu, t, off);
                if (lane >= off) t += n;
            }
            ws[lane] = t;
        }
        __syncthreads();
        unsigned excl = s - v + (wid ? ws[wid-1] : 0u) + carry;
        g_off[i] = excl; g_cur[i] = excl;
        __syncthreads();
        if (tid == 1023) carry_s = excl + v;
        __syncthreads();
    }
}

// ---------------- scatter into morton-sorted order ----------------
__global__ void k_scatter(const float* __restrict__ xyz) {
    int i = blockIdx.x*256 + threadIdx.x;
    int b = i >> 13;
    float lox = fdec(g_bblo[b*3]),   loy = fdec(g_bblo[b*3+1]), loz = fdec(g_bblo[b*3+2]);
    float ivx = (float)G/(fdec(g_bbhi[b*3])   - lox + 1e-4f);
    float ivy = (float)G/(fdec(g_bbhi[b*3+1]) - loy + 1e-4f);
    float ivz = (float)G/(fdec(g_bbhi[b*3+2]) - loz + 1e-4f);
    float x = xyz[3*i], y = xyz[3*i+1], z = xyz[3*i+2];
    unsigned m = morton3(cell1(x,lox,ivx), cell1(y,loy,ivy), cell1(z,loz,ivz));
    unsigned pos = atomicAdd(&g_cur[b*NCELLS + m], 1u);
    int slot = b*NPTS + (int)pos;
    g_spts[slot] = g_xyzw[i];
    g_sidx[slot] = i & (NPTS-1);
}

// ---------------- per-tile AABB (exact, from points) ----------------
__global__ void k_taabb() {   // 32 blocks x 256 (8 warps)
    int w = threadIdx.x >> 5, lane = threadIdx.x & 31;
    int tile = blockIdx.x*8 + w;
    float xmn = CUDART_INF_F, ymn = CUDART_INF_F, zmn = CUDART_INF_F;
    float xmx = -CUDART_INF_F, ymx = -CUDART_INF_F, zmx = -CUDART_INF_F;
    #pragma unroll
    for (int i = 0; i < TPW/32; ++i) {
        float4 c = g_spts[tile*TPW + lane + i*32];
        float x = -0.5f*c.x, y = -0.5f*c.y, z = -0.5f*c.z;
        xmn = fminf(xmn, x); xmx = fmaxf(xmx, x);
        ymn = fminf(ymn, y); ymx = fmaxf(ymx, y);
        zmn = fminf(zmn, z); zmx = fmaxf(zmx, z);
    }
    #pragma unroll
    for (int off = 16; off; off >>= 1) {
        xmn = fminf(xmn, __shfl_xor_sync(0xffffffffu, xmn, off));
        xmx = fmaxf(xmx, __shfl_xor_sync(0xffffffffu, xmx, off));
        ymn = fminf(ymn, __shfl_xor_sync(0xffffffffu, ymn, off));
        ymx = fmaxf(ymx, __shfl_xor_sync(0xffffffffu, ymx, off));
        zmn = fminf(zmn, __shfl_xor_sync(0xffffffffu, zmn, off));
        zmx = fmaxf(zmx, __shfl_xor_sync(0xffffffffu, zmx, off));
    }
    if (lane == 0) {
        g_tlo[tile] = make_float4(xmn, ymn, zmn, 0.f);
        g_thi[tile] = make_float4(xmx, ymx, zmx, 0.f);
    }
}

// ---------------- kNN: AABB-pruned tile scan, 4 warps/group (R11 version) ----------------
__global__ void __launch_bounds__(128) k_knn() {
    __shared__ float4 tile_s[NW][TPW];     // 8KB
    __shared__ float  sth[NW][32];         // per-(warp,query) 16th-dist^2
    __shared__ float  md[KNN*NW*32];       // merge keys
    __shared__ int    mi[KNN*NW*32];       // merge slot ids

    int w = threadIdx.x >> 5, lane = threadIdx.x & 31;
    int qslot0 = blockIdx.x*32;            // 32 consecutive morton-sorted queries
    int b = qslot0 >> 13, bbase = b*NPTS;
    int ql = qslot0 & (NPTS-1);
    int slot = qslot0 + lane;
    float4 qc = g_spts[slot];
    float qx = -0.5f*qc.x, qy = -0.5f*qc.y, qz = -0.5f*qc.z, qw = qc.w;

    volatile float* sv = &sth[0][0];
    sth[w][lane] = CUDART_INF_F;

    float kk[KNN]; int ii[KNN];
    #pragma unroll
    for (int s = 0; s < KNN; ++s) { kk[s] = CUDART_INF_F; ii[s] = 0; }
    float pkey = 0.f; int psl = 0; bool pval = false;

#define KNN_FLUSH() do {                                              \
        float ck = pkey; int ci = psl;                                \
        _Pragma("unroll")                                             \
        for (int s = 0; s < KNN; ++s) {                               \
            bool sw = ck < kk[s];                                     \
            float tk = kk[s]; int ti = ii[s];                         \
            kk[s] = sw ? ck : tk;  ii[s] = sw ? ci : ti;              \
            ck = sw ? tk : ck;     ci = sw ? ti : ci;                 \
        }                                                             \
    } while (0)

#define SCAN_TILE(T0, CAP) do {                                       \
        __syncwarp();                                                 \
        _Pragma("unroll")                                             \
        for (int i_ = 0; i_ < TPW/32; ++i_)                           \
            tile_s[w][lane + i_*32] = g_spts[bbase + (T0) + lane + i_*32]; \
        __syncwarp();                                                 \
        float thr = fminf(kk[KNN-1], (CAP));                          \
        _Pragma("unroll 8")                                           \
        for (int j_ = 0; j_ < TPW; ++j_) {                            \
            float4 c = tile_s[w][j_];                                 \
            float key = fmaf(c.x, qx, fmaf(c.y, qy, fmaf(c.z, qz, c.w))); \
            bool hit = key < thr;                                     \
            if (__any_sync(0xffffffffu, hit && pval)) {               \
                if (pval) { KNN_FLUSH(); thr = fminf(kk[KNN-1], (CAP)); } \
                pval = false;                                         \
            }                                                         \
            if (hit) { pkey = key; psl = (T0) + j_; pval = true; }    \
        }                                                             \
        if (__any_sync(0xffffffffu, pval)) {                          \
            if (pval) KNN_FLUSH();                                    \
            pval = false;                                             \
        }                                                             \
        sth[w][lane] = kk[KNN-1] + qw;                                \
    } while (0)

    __syncthreads();
    int tq = ql >> 7;                       // own tile (holds all 32 queries)
    if (w == 0) SCAN_TILE(tq*TPW, CUDART_INF_F);   // warm-start: compact 3D blob
    __syncthreads();

    // each warp handles 16 of the 64 tiles, pruned by exact point-AABB distance
    for (int t = w; t < NTILES; t += NW) {
        if (t == tq) continue;
        float d2s = fminf(fminf(sv[lane], sv[32+lane]), fminf(sv[64+lane], sv[96+lane]));
        d2s = fminf(d2s, kk[KNN-1] + qw);
        float4 blo = g_tlo[b*NTILES + t];
        float4 bhi = g_thi[b*NTILES + t];
        float dx = fmaxf(fmaxf(blo.x - qx, qx - bhi.x), 0.f);
        float dy = fmaxf(fmaxf(blo.y - qy, qy - bhi.y), 0.f);
        float dz = fmaxf(fmaxf(blo.z - qz, qz - bhi.z), 0.f);
        float cd2 = fmaf(dx, dx, fmaf(dy, dy, dz*dz));
        if (__all_sync(0xffffffffu, cd2 >= d2s + 1e-4f)) continue;  // margin > key rounding
        SCAN_TILE(t*TPW, d2s - qw);
    }
#undef SCAN_TILE
#undef KNN_FLUSH

    // ---- 4-way merge of sorted 16-lists (disjoint tiles -> no duplicates) ----
    #pragma unroll
    for (int s = 0; s < KNN; ++s) {
        md[s*(NW*32) + w*32 + lane] = kk[s];
        mi[s*(NW*32) + w*32 + lane] = ii[s];
    }
    __syncthreads();
    if (w == 0) {
        int p0 = 0, p1 = 0, p2 = 0, p3 = 0;
        int oq = g_sidx[slot];
        int* op = g_idx + (size_t)(bbase + oq)*KNN;
        #pragma unroll
        for (int s = 0; s < KNN; ++s) {
            float h0 = md[p0*128 +  0 + lane];
            float h1 = md[p1*128 + 32 + lane];
            float h2 = md[p2*128 + 64 + lane];
            float h3 = md[p3*128 + 96 + lane];
            float best = h0; int bw = 0;
            if (h1 < best) { best = h1; bw = 1; }
            if (h2 < best) { best = h2; bw = 2; }
            if (h3 < best) { best = h3; bw = 3; }
            int pj = (bw == 0) ? p0 : (bw == 1) ? p1 : (bw == 2) ? p2 : p3;
            int sl = mi[pj*128 + bw*32 + lane];
            op[s] = g_sidx[bbase + sl];
            if (bw == 0) ++p0; else if (bw == 1) ++p1; else if (bw == 2) ++p2; else ++p3;
        }
    }
}

// ---------------- fused attention (warp per point): fbar instead of vbar ----------------
__global__ void k_fuse(const float* __restrict__ xyz, const float* __restrict__ Wp1,
                       const float* __restrict__ bp1, const float* __restrict__ feat) {
    __shared__ float sw0[D], sw1[D], sw2[D], sb1[D], srs[D];
    int tid = threadIdx.x;
    sw0[tid] = Wp1[tid]; sw1[tid] = Wp1[D + tid]; sw2[tid] = Wp1[2*D + tid];
    sb1[tid] = bp1[tid]; srs[tid] = g_wp2rs[tid];
    __syncthreads();

    int warp = tid >> 5, lane = tid & 31;
    int p = blockIdx.x*4 + warp;
    int bbase = p & ~(NPTS-1);

    float w0[4], w1[4], w2[4], b1r[4], rs[4];
    #pragma unroll
    for (int i = 0; i < 4; ++i) {
        int d = lane + 32*i;
        w0[i] = sw0[d]; w1[i] = sw1[d]; w2[i] = sw2[d]; b1r[i] = sb1[d]; rs[i] = srs[d];
    }

    float rx = 0.f, ry = 0.f, rz = 0.f, ks = 0.f; int row = 0;
    if (lane < KNN) {
        int nb = g_idx[(size_t)p*KNN + lane];
        row = bbase + nb;
        float qx = xyz[3*p], qy = xyz[3*p+1], qz = xyz[3*p+2];
        rx = qx - xyz[3*row]; ry = qy - xyz[3*row+1]; rz = qz - xyz[3*row+2];
        ks = g_ksum[row];
    }

    // pass 1: attention logits  score_k = h_k . rowsum(Wp2) - ksum_k
    float mysc = -CUDART_INF_F;
    #pragma unroll
    for (int k = 0; k < KNN; ++k) {
        float bx = __shfl_sync(0xffffffffu, rx, k);
        float by = __shfl_sync(0xffffffffu, ry, k);
        float bz = __shfl_sync(0xffffffffu, rz, k);
        float part = 0.f;
        #pragma unroll
        for (int i = 0; i < 4; ++i) {
            float h = fmaf(bx, w0[i], fmaf(by, w1[i], fmaf(bz, w2[i], b1r[i])));
            h = fmaxf(h, 0.f);
            part = fmaf(h, rs[i], part);
        }
        #pragma unroll
        for (int off = 16; off; off >>= 1) part += __shfl_xor_sync(0xffffffffu, part, off);
        if (lane == k) mysc = part - ks;
    }
    // softmax over the 16 neighbor lanes
    float mx = mysc;
    #pragma unroll
    for (int off = 16; off; off >>= 1) mx = fmaxf(mx, __shfl_xor_sync(0xffffffffu, mx, off));
    float e = (lane < KNN) ? __expf(mysc - mx) : 0.f;
    float ssum = e;
    #pragma unroll
    for (int off = 16; off; off >>= 1) ssum += __shfl_xor_sync(0xffffffffu, ssum, off);
    float attn = e / ssum;

    // pass 2: hbar = sum attn*h, fbar = sum attn*feat
    float hb[4] = {0,0,0,0}, fb[4] = {0,0,0,0};
    #pragma unroll
    for (int k = 0; k < KNN; ++k) {
        float a  = __shfl_sync(0xffffffffu, attn, k);
        float bx = __shfl_sync(0xffffffffu, rx, k);
        float by = __shfl_sync(0xffffffffu, ry, k);
        float bz = __shfl_sync(0xffffffffu, rz, k);
        int   r  = __shfl_sync(0xffffffffu, row, k);
        const float* fr = feat + (size_t)r*D;
        #pragma unroll
        for (int i = 0; i < 4; ++i) {
            int d = lane + 32*i;
            float h = fmaf(bx, w0[i], fmaf(by, w1[i], fmaf(bz, w2[i], b1r[i])));
            h = fmaxf(h, 0.f);
            hb[i] = fmaf(a, h, hb[i]);
            fb[i] = fmaf(a, fr[d], fb[i]);
        }
    }
    #pragma unroll
    for (int i = 0; i < 4; ++i) {
        int d = lane + 32*i;
        g_hbar[(size_t)p*D + d] = hb[i];
        g_fbar[(size_t)p*D + d] = fb[i];
    }
}

// ---------------- out = feat + gamma*(fbar@Wvo + hbar@Wf + cvec) ----------------
__global__ void k_out(const float* __restrict__ feat, const float* __restrict__ gamma,
                      float* __restrict__ out) {
    __shared__ float As[16][132];
    __shared__ float Ws[16][132];
    int m0 = blockIdx.x*128;
    int tx = threadIdx.x & 15, ty = threadIdx.x >> 4;
    float acc[8][8];
    #pragma unroll
    for (int i = 0; i < 8; ++i)
        #pragma unroll
        for (int j = 0; j < 8; ++j) acc[i][j] = 0.f;

    for (int ph = 0; ph < 2; ++ph) {
        const float* A = ph ? g_hbar : g_fbar;
        const float* W = ph ? g_wf   : g_wvo;
        for (int kc = 0; kc < D; kc += 16) {
            __syncthreads();
            { int c = threadIdx.x & 3, r = threadIdx.x >> 2;
              #pragma unroll
              for (int rr = 0; rr < 2; ++rr) {
                  int mm = r + rr*64;
                  float4 v = *(const float4*)&A[(size_t)(m0+mm)*D + kc + c*4];
                  As[c*4+0][mm] = v.x; As[c*4+1][mm] = v.y;
                  As[c*4+2][mm] = v.z; As[c*4+3][mm] = v.w;
              }
            }
            { int k = threadIdx.x >> 5, c4 = threadIdx.x & 31;
              #pragma unroll
              for (int kk = 0; kk < 2; ++kk) {
                  float4 v = *(const float4*)&W[(size_t)(kc + k + kk*8)*D + c4*4];
                  Ws[k + kk*8][c4*4+0] = v.x; Ws[k + kk*8][c4*4+1] = v.y;
                  Ws[k + kk*8][c4*4+2] = v.z; Ws[k + kk*8][c4*4+3] = v.w;
              }
            }
            __syncthreads();
            #pragma unroll
            for (int k = 0; k < 16; ++k) {
                float a[8], bb[8];
                #pragma unroll
                for (int i = 0; i < 8; ++i) a[i]  = As[k][ty*8 + i];
                #pragma unroll
                for (int j = 0; j < 8; ++j) bb[j] = Ws[k][tx*8 + j];
                #pragma unroll
                for (int i = 0; i < 8; ++i)
                    #pragma unroll
                    for (int j = 0; j < 8; ++j) acc[i][j] = fmaf(a[i], bb[j], acc[i][j]);
            }
        }
    }
    float g = *gamma;
    float cv[8];
    #pragma unroll
    for (int j = 0; j < 8; ++j) cv[j] = g_cvec[tx*8 + j];
    #pragma unroll
    for (int i = 0; i < 8; ++i) {
        int m = m0 + ty*8 + i;
        float4 f0 = *(const float4*)&feat[(size_t)m*D + tx*8];
        float4 f1 = *(const float4*)&feat[(size_t)m*D + tx*8 + 4];
        float o0 = f0.x + g*(acc[i][0] + cv[0]);
        float o1 = f0.y + g*(acc[i][1] + cv[1]);
        float o2 = f0.z + g*(acc[i][2] + cv[2]);
        float o3 = f0.w + g*(acc[i][3] + cv[3]);
        float o4 = f1.x + g*(acc[i][4] + cv[4]);
        float o5 = f1.y + g*(acc[i][5] + cv[5]);
        float o6 = f1.z + g*(acc[i][6] + cv[6]);
        float o7 = f1.w + g*(acc[i][7] + cv[7]);
        *(float4*)&out[(size_t)m*D + tx*8]     = make_float4(o0, o1, o2, o3);
        *(float4*)&out[(size_t)m*D + tx*8 + 4] = make_float4(o4, o5, o6, o7);
    }
}

// ---------------- launch ----------------
extern "C" void kernel_launch(void* const* d_in, const int* in_sizes, int n_in,
                              void* d_out, int out_size) {
    const float* xyz  = (const float*)d_in[0];
    const float* feat = (const float*)d_in[1];
    // d_in[2]=Wq, d_in[3]=bq, d_in[5]=bk : mathematically cancel in softmax, unused
    const float* Wk   = (const float*)d_in[4];
    const float* Wv   = (const float*)d_in[6];
    const float* bv   = (const float*)d_in[7];
    const float* Wp1  = (const float*)d_in[8];
    const float* bp1  = (const float*)d_in[9];
    const float* Wp2  = (const float*)d_in[10];
    const float* bp2  = (const float*)d_in[11];
    const float* Wo   = (const float*)d_in[12];
    const float* bo   = (const float*)d_in[13];
    const float* gmm  = (const float*)d_in[14];
    float* out = (float*)d_out;

    k_zero<<<NB*NCELLS/256, 256>>>();
    k_weights<<<1, 128>>>(Wk, Wp2, bp2, Wo, bo, bv);
    k_wfused<<<128, 256>>>(Wp2, Wv, Wo);
    k_prep<<<BN/8, 256>>>(xyz, feat);
    k_bbox<<<dim3(32, NB), 256>>>(xyz);
    k_hist<<<BN/256, 256>>>(xyz);
    k_scan<<<NB, 1024>>>();
    k_scatter<<<BN/256, 256>>>(xyz);
    k_taabb<<<NB*NTILES/8, 256>>>();
    k_knn<<<BN/32, 128>>>();
    k_fuse<<<BN/4, 128>>>(xyz, Wp1, bp1, feat);
    k_out<<<BN/128, 256>>>(feat, gmm, out);
}

// round 16
// speedup vs baseline: 1.5200x; 1.1496x over previous
#include <cuda_runtime.h>
#include <math.h>
#include <math_constants.h>

#define NB   4
#define NPTS 8192
#define BN   (NB*NPTS)   // 32768
#define D    128
#define KNN  16
#define G    16
#define NCELLS (G*G*G)   // 4096 cells per batch
#define TPW  64          // tile slots per warp (halved: shorter warm-start, finer pruning)
#define NTILES (NPTS/TPW) // 128 tiles per batch
#define NW   4           // warps per query group

// ---------------- scratch (static device allocations) ----------------
__device__ float4   g_xyzw[BN];        // (-2x,-2y,-2z, |x|^2) per point (orig order)
__device__ float4   g_spts[BN];        // same, sorted by (batch, morton cell)
__device__ int      g_sidx[BN];        // sorted slot -> original local idx
__device__ unsigned g_cnt[NB*NCELLS];  // histogram
__device__ unsigned g_off[NB*NCELLS];  // cell start offsets (batch-local)
__device__ unsigned g_cur[NB*NCELLS];  // scatter cursors
__device__ unsigned g_bblo[NB*3], g_bbhi[NB*3];  // encoded bbox
__device__ float4   g_tlo[NB*NTILES];  // per-tile AABB min (xyz)
__device__ float4   g_thi[NB*NTILES];  // per-tile AABB max (xyz)
__device__ float  g_ksum[BN];          // feat . rowsum(Wk)
__device__ int    g_idx[BN*KNN];       // knn indices (within batch)
__device__ float  g_hbar[BN*D];        // sum_k attn_k * h_k
__device__ float  g_fbar[BN*D];        // sum_k attn_k * feat_k
__device__ float  g_wkrs[D];           // rowsum over out-dim of Wk
__device__ float  g_wp2rs[D];          // rowsum over out-dim of Wp2
__device__ float  g_cvec[D];           // (bv + bp2) @ Wo + bo
__device__ float  g_wf[D*D];           // Wp2 @ Wo
__device__ float  g_wvo[D*D];          // Wv @ Wo

// ---------------- helpers ----------------
__device__ __forceinline__ unsigned fenc(float f) {
    unsigned u = __float_as_uint(f);
    return (u & 0x80000000u) ? ~u : (u | 0x80000000u);
}
__device__ __forceinline__ float fdec(unsigned u) {
    return (u & 0x80000000u) ? __uint_as_float(u ^ 0x80000000u) : __uint_as_float(~u);
}
__device__ __forceinline__ unsigned msp4(unsigned x) {
    return (x & 1u) | ((x & 2u) << 2) | ((x & 4u) << 4) | ((x & 8u) << 6);
}
__device__ __forceinline__ unsigned morton3(int cx, int cy, int cz) {
    return msp4((unsigned)cx) | (msp4((unsigned)cy) << 1) | (msp4((unsigned)cz) << 2);
}
__device__ __forceinline__ int cell1(float x, float lo, float inv) {
    int v = (int)((x - lo) * inv);
    return v < 0 ? 0 : (v > G-1 ? G-1 : v);
}

// ---------------- init ----------------
__global__ void k_zero() {   // 64 blocks x 256
    int i = blockIdx.x*256 + threadIdx.x;
    g_cnt[i] = 0;
    if (i < NB*3) { g_bblo[i] = 0xFFFFFFFFu; g_bbhi[i] = 0u; }
}

// ---------------- weight prep ----------------
__global__ void k_weights(const float* __restrict__ Wk, const float* __restrict__ Wp2,
                          const float* __restrict__ bp2, const float* __restrict__ Wo,
                          const float* __restrict__ bo, const float* __restrict__ bv) {
    int i = threadIdx.x;
    float a = 0.f, b = 0.f, c = bo[i];
    for (int j = 0; j < D; ++j) { a += Wk[i*D + j]; b += Wp2[i*D + j]; }
    for (int k = 0; k < D; ++k) c = fmaf(bp2[k] + bv[k], Wo[k*D + i], c);
    g_wkrs[i] = a; g_wp2rs[i] = b; g_cvec[i] = c;
}

// Wf = Wp2 @ Wo  and  Wvo = Wv @ Wo   (128 blocks x 256)
__global__ void k_wfused(const float* __restrict__ Wp2, const float* __restrict__ Wv,
                         const float* __restrict__ Wo) {
    int d = threadIdx.x & (D-1);
    int r = blockIdx.x*2 + (threadIdx.x >> 7);   // 0..255
    const float* A = (r < D) ? Wp2 : Wv;
    float* O = (r < D) ? g_wf : g_wvo;
    int i = r & (D-1);
    float a = 0.f;
    for (int k = 0; k < D; ++k) a = fmaf(A[i*D + k], Wo[k*D + d], a);
    O[i*D + d] = a;
}

// ---------------- per-point prep: xyzw + ksum ----------------
__global__ void k_prep(const float* __restrict__ xyz, const float* __restrict__ feat) {
    int warp = threadIdx.x >> 5, lane = threadIdx.x & 31;
    int p = blockIdx.x*8 + warp;
    const float* fr = feat + (size_t)p*D;
    float acc = 0.f;
    #pragma unroll
    for (int i = 0; i < 4; ++i) {
        int d = lane + 32*i;
        acc = fmaf(fr[d], g_wkrs[d], acc);
    }
    #pragma unroll
    for (int off = 16; off; off >>= 1) acc += __shfl_xor_sync(0xffffffffu, acc, off);
    if (lane == 0) {
        g_ksum[p] = acc;
        float x = xyz[3*p], y = xyz[3*p+1], z = xyz[3*p+2];
        g_xyzw[p] = make_float4(-2.f*x, -2.f*y, -2.f*z, x*x + y*y + z*z);
    }
}

// ---------------- bbox per batch (3 dims) ----------------
__global__ void k_bbox(const float* __restrict__ xyz) {   // grid (32, NB), block 256
    int b = blockIdx.y;
    __shared__ unsigned slo[3], shi[3];
    if (threadIdx.x < 3) { slo[threadIdx.x] = 0xFFFFFFFFu; shi[threadIdx.x] = 0u; }
    __syncthreads();
    int p = blockIdx.x*256 + threadIdx.x;
    if (p < NPTS) {
        const float* r = xyz + (size_t)(b*NPTS + p)*3;
        #pragma unroll
        for (int a = 0; a < 3; ++a) {
            unsigned e = fenc(r[a]);
            atomicMin(&slo[a], e); atomicMax(&shi[a], e);
        }
    }
    __syncthreads();
    if (threadIdx.x < 3) {
        atomicMin(&g_bblo[b*3 + threadIdx.x], slo[threadIdx.x]);
        atomicMax(&g_bbhi[b*3 + threadIdx.x], shi[threadIdx.x]);
    }
}

// ---------------- histogram over morton cells ----------------
__global__ void k_hist(const float* __restrict__ xyz) {
    int i = blockIdx.x*256 + threadIdx.x;
    int b = i >> 13;
    float lox = fdec(g_bblo[b*3]),   loy = fdec(g_bblo[b*3+1]), loz = fdec(g_bblo[b*3+2]);
    float ivx = (float)G/(fdec(g_bbhi[b*3])   - lox + 1e-4f);
    float ivy = (float)G/(fdec(g_bbhi[b*3+1]) - loy + 1e-4f);
    float ivz = (float)G/(fdec(g_bbhi[b*3+2]) - loz + 1e-4f);
    float x = xyz[3*i], y = xyz[3*i+1], z = xyz[3*i+2];
    unsigned m = morton3(cell1(x,lox,ivx), cell1(y,loy,ivy), cell1(z,loz,ivz));
    atomicAdd(&g_cnt[b*NCELLS + m], 1u);
}

// ---------------- exclusive scan per batch (4096 cells) ----------------
__global__ void k_scan() {   // grid NB, block 1024
    int b = blockIdx.x;
    int tid = threadIdx.x, lane = tid & 31, wid = tid >> 5;
    __shared__ unsigned ws[32];
    __shared__ unsigned carry_s;
    if (tid == 0) carry_s = 0;
    __syncthreads();
    for (int it = 0; it < NCELLS/1024; ++it) {
        unsigned carry = carry_s;
        int i = b*NCELLS + it*1024 + tid;
        unsigned v = g_cnt[i];
        unsigned s = v;
        #pragma unroll
        for (int off = 1; off < 32; off <<= 1) {
            unsigned n = __shfl_up_sync(0xffffffffu, s, off);
            if (lane >= off) s += n;
        }
        if (lane == 31) ws[wid] = s;
        __syncthreads();
        if (wid == 0) {
            unsigned t = ws[lane];
            #pragma unroll
            for (int off = 1; off < 32; off <<= 1) {
                unsigned n = __shfl_up_sync(0xffffffffu, t, off);
                if (lane >= off) t += n;
            }
            ws[lane] = t;
        }
        __syncthreads();
        unsigned excl = s - v + (wid ? ws[wid-1] : 0u) + carry;
        g_off[i] = excl; g_cur[i] = excl;
        __syncthreads();
        if (tid == 1023) carry_s = excl + v;
        __syncthreads();
    }
}

// ---------------- scatter into morton-sorted order ----------------
__global__ void k_scatter(const float* __restrict__ xyz) {
    int i = blockIdx.x*256 + threadIdx.x;
    int b = i >> 13;
    float lox = fdec(g_bblo[b*3]),   loy = fdec(g_bblo[b*3+1]), loz = fdec(g_bblo[b*3+2]);
    float ivx = (float)G/(fdec(g_bbhi[b*3])   - lox + 1e-4f);
    float ivy = (float)G/(fdec(g_bbhi[b*3+1]) - loy + 1e-4f);
    float ivz = (float)G/(fdec(g_bbhi[b*3+2]) - loz + 1e-4f);
    float x = xyz[3*i], y = xyz[3*i+1], z = xyz[3*i+2];
    unsigned m = morton3(cell1(x,lox,ivx), cell1(y,loy,ivy), cell1(z,loz,ivz));
    unsigned pos = atomicAdd(&g_cur[b*NCELLS + m], 1u);
    int slot = b*NPTS + (int)pos;
    g_spts[slot] = g_xyzw[i];
    g_sidx[slot] = i & (NPTS-1);
}

// ---------------- per-tile AABB (exact, from points) ----------------
__global__ void k_taabb() {   // NB*NTILES/8 blocks x 256 (8 warps)
    int w = threadIdx.x >> 5, lane = threadIdx.x & 31;
    int tile = blockIdx.x*8 + w;
    float xmn = CUDART_INF_F, ymn = CUDART_INF_F, zmn = CUDART_INF_F;
    float xmx = -CUDART_INF_F, ymx = -CUDART_INF_F, zmx = -CUDART_INF_F;
    #pragma unroll
    for (int i = 0; i < TPW/32; ++i) {
        float4 c = g_spts[tile*TPW + lane + i*32];
        float x = -0.5f*c.x, y = -0.5f*c.y, z = -0.5f*c.z;
        xmn = fminf(xmn, x); xmx = fmaxf(xmx, x);
        ymn = fminf(ymn, y); ymx = fmaxf(ymx, y);
        zmn = fminf(zmn, z); zmx = fmaxf(zmx, z);
    }
    #pragma unroll
    for (int off = 16; off; off >>= 1) {
        xmn = fminf(xmn, __shfl_xor_sync(0xffffffffu, xmn, off));
        xmx = fmaxf(xmx, __shfl_xor_sync(0xffffffffu, xmx, off));
        ymn = fminf(ymn, __shfl_xor_sync(0xffffffffu, ymn, off));
        ymx = fmaxf(ymx, __shfl_xor_sync(0xffffffffu, ymx, off));
        zmn = fminf(zmn, __shfl_xor_sync(0xffffffffu, zmn, off));
        zmx = fmaxf(zmx, __shfl_xor_sync(0xffffffffu, zmx, off));
    }
    if (lane == 0) {
        g_tlo[tile] = make_float4(xmn, ymn, zmn, 0.f);
        g_thi[tile] = make_float4(xmx, ymx, zmx, 0.f);
    }
}

// ---------------- kNN: AABB-pruned center-out tile scan, 4 warps/group ----------------
__global__ void __launch_bounds__(128) k_knn() {
    __shared__ float4 tile_s[NW][TPW];     // 4KB
    __shared__ float  sth[NW][32];         // per-(warp,query) 16th-dist^2
    __shared__ float  md[KNN*NW*32];       // merge keys
    __shared__ int    mi[KNN*NW*32];       // merge slot ids

    int w = threadIdx.x >> 5, lane = threadIdx.x & 31;
    int qslot0 = blockIdx.x*32;            // 32 consecutive morton-sorted queries
    int b = qslot0 >> 13, bbase = b*NPTS;
    int ql = qslot0 & (NPTS-1);
    int slot = qslot0 + lane;
    float4 qc = g_spts[slot];
    float qx = -0.5f*qc.x, qy = -0.5f*qc.y, qz = -0.5f*qc.z, qw = qc.w;

    volatile float* sv = &sth[0][0];
    sth[w][lane] = CUDART_INF_F;

    float kk[KNN]; int ii[KNN];
    #pragma unroll
    for (int s = 0; s < KNN; ++s) { kk[s] = CUDART_INF_F; ii[s] = 0; }
    float pkey = 0.f; int psl = 0; bool pval = false;

#define KNN_FLUSH() do {                                              \
        float ck = pkey; int ci = psl;                                \
        _Pragma("unroll")                                             \
        for (int s = 0; s < KNN; ++s) {                               \
            bool sw = ck < kk[s];                                     \
            float tk = kk[s]; int ti = ii[s];                         \
            kk[s] = sw ? ck : tk;  ii[s] = sw ? ci : ti;              \
            ck = sw ? tk : ck;     ci = sw ? ti : ci;                 \
        }                                                             \
    } while (0)

#define SCAN_TILE(T0, CAP) do {                                       \
        __syncwarp();                                                 \
        _Pragma("unroll")                                             \
        for (int i_ = 0; i_ < TPW/32; ++i_)                           \
            tile_s[w][lane + i_*32] = g_spts[bbase + (T0) + lane + i_*32]; \
        __syncwarp();                                                 \
        float thr = fminf(kk[KNN-1], (CAP));                          \
        _Pragma("unroll 8")                                           \
        for (int j_ = 0; j_ < TPW; ++j_) {                            \
            float4 c = tile_s[w][j_];                                 \
            float key = fmaf(c.x, qx, fmaf(c.y, qy, fmaf(c.z, qz, c.w))); \
            bool hit = key < thr;                                     \
            if (__any_sync(0xffffffffu, hit && pval)) {               \
                if (pval) { KNN_FLUSH(); thr = fminf(kk[KNN-1], (CAP)); } \
                pval = false;                                         \
            }                                                         \
            if (hit) { pkey = key; psl = (T0) + j_; pval = true; }    \
        }                                                             \
        if (__any_sync(0xffffffffu, pval)) {                          \
            if (pval) KNN_FLUSH();                                    \
            pval = false;                                             \
        }                                                             \
        sth[w][lane] = kk[KNN-1] + qw;                                \
    } while (0)

    __syncthreads();
    int tq = ql / TPW;                      // own tile (contains all 32 queries)
    if (w == 0) SCAN_TILE(tq*TPW, CUDART_INF_F);   // warm-start: compact 3D blob
    __syncthreads();

    // center-out tile order: t = tq+1, tq-1, tq+2, tq-2, ... dealt round-robin
    // across the 4 warps. Near (likely-surviving) tiles are scanned first,
    // tightening the shared bound before far tiles are prune-tested.
    for (int j = w; j < 2*(NTILES-1); j += NW) {
        int off = (j >> 1) + 1;
        int t = (j & 1) ? tq - off : tq + off;
        if ((unsigned)t >= NTILES) continue;
        float d2s = fminf(fminf(sv[lane], sv[32+lane]), fminf(sv[64+lane], sv[96+lane]));
        d2s = fminf(d2s, kk[KNN-1] + qw);
        float4 blo = g_tlo[b*NTILES + t];
        float4 bhi = g_thi[b*NTILES + t];
        float dx = fmaxf(fmaxf(blo.x - qx, qx - bhi.x), 0.f);
        float dy = fmaxf(fmaxf(blo.y - qy, qy - bhi.y), 0.f);
        float dz = fmaxf(fmaxf(blo.z - qz, qz - bhi.z), 0.f);
        float cd2 = fmaf(dx, dx, fmaf(dy, dy, dz*dz));
        if (__all_sync(0xffffffffu, cd2 >= d2s + 1e-4f)) continue;  // margin > key rounding
        SCAN_TILE(t*TPW, d2s - qw);
    }
#undef SCAN_TILE
#undef KNN_FLUSH

    // ---- 4-way merge of sorted 16-lists (disjoint tiles -> no duplicates) ----
    #pragma unroll
    for (int s = 0; s < KNN; ++s) {
        md[s*(NW*32) + w*32 + lane] = kk[s];
        mi[s*(NW*32) + w*32 + lane] = ii[s];
    }
    __syncthreads();
    if (w == 0) {
        int p0 = 0, p1 = 0, p2 = 0, p3 = 0;
        int oq = g_sidx[slot];
        int* op = g_idx + (size_t)(bbase + oq)*KNN;
        #pragma unroll
        for (int s = 0; s < KNN; ++s) {
            float h0 = md[p0*128 +  0 + lane];
            float h1 = md[p1*128 + 32 + lane];
            float h2 = md[p2*128 + 64 + lane];
            float h3 = md[p3*128 + 96 + lane];
            float best = h0; int bw = 0;
            if (h1 < best) { best = h1; bw = 1; }
            if (h2 < best) { best = h2; bw = 2; }
            if (h3 < best) { best = h3; bw = 3; }
            int pj = (bw == 0) ? p0 : (bw == 1) ? p1 : (bw == 2) ? p2 : p3;
            int sl = mi[pj*128 + bw*32 + lane];
            op[s] = g_sidx[bbase + sl];
            if (bw == 0) ++p0; else if (bw == 1) ++p1; else if (bw == 2) ++p2; else ++p3;
        }
    }
}

// ---------------- fused attention (warp per point): fbar instead of vbar ----------------
__global__ void k_fuse(const float* __restrict__ xyz, const float* __restrict__ Wp1,
                       const float* __restrict__ bp1, const float* __restrict__ feat) {
    __shared__ float sw0[D], sw1[D], sw2[D], sb1[D], srs[D];
    int tid = threadIdx.x;
    sw0[tid] = Wp1[tid]; sw1[tid] = Wp1[D + tid]; sw2[tid] = Wp1[2*D + tid];
    sb1[tid] = bp1[tid]; srs[tid] = g_wp2rs[tid];
    __syncthreads();

    int warp = tid >> 5, lane = tid & 31;
    int p = blockIdx.x*4 + warp;
    int bbase = p & ~(NPTS-1);

    float w0[4], w1[4], w2[4], b1r[4], rs[4];
    #pragma unroll
    for (int i = 0; i < 4; ++i) {
        int d = lane + 32*i;
        w0[i] = sw0[d]; w1[i] = sw1[d]; w2[i] = sw2[d]; b1r[i] = sb1[d]; rs[i] = srs[d];
    }

    float rx = 0.f, ry = 0.f, rz = 0.f, ks = 0.f; int row = 0;
    if (lane < KNN) {
        int nb = g_idx[(size_t)p*KNN + lane];
        row = bbase + nb;
        float qx = xyz[3*p], qy = xyz[3*p+1], qz = xyz[3*p+2];
        rx = qx - xyz[3*row]; ry = qy - xyz[3*row+1]; rz = qz - xyz[3*row+2];
        ks = g_ksum[row];
    }

    // pass 1: attention logits  score_k = h_k . rowsum(Wp2) - ksum_k
    float mysc = -CUDART_INF_F;
    #pragma unroll
    for (int k = 0; k < KNN; ++k) {
        float bx = __shfl_sync(0xffffffffu, rx, k);
        float by = __shfl_sync(0xffffffffu, ry, k);
        float bz = __shfl_sync(0xffffffffu, rz, k);
        float part = 0.f;
        #pragma unroll
        for (int i = 0; i < 4; ++i) {
            float h = fmaf(bx, w0[i], fmaf(by, w1[i], fmaf(bz, w2[i], b1r[i])));
            h = fmaxf(h, 0.f);
            part = fmaf(h, rs[i], part);
        }
        #pragma unroll
        for (int off = 16; off; off >>= 1) part += __shfl_xor_sync(0xffffffffu, part, off);
        if (lane == k) mysc = part - ks;
    }
    // softmax over the 16 neighbor lanes
    float mx = mysc;
    #pragma unroll
    for (int off = 16; off; off >>= 1) mx = fmaxf(mx, __shfl_xor_sync(0xffffffffu, mx, off));
    float e = (lane < KNN) ? __expf(mysc - mx) : 0.f;
    float ssum = e;
    #pragma unroll
    for (int off = 16; off; off >>= 1) ssum += __shfl_xor_sync(0xffffffffu, ssum, off);
    float attn = e / ssum;

    // pass 2: hbar = sum attn*h, fbar = sum attn*feat
    float hb[4] = {0,0,0,0}, fb[4] = {0,0,0,0};
    #pragma unroll
    for (int k = 0; k < KNN; ++k) {
        float a  = __shfl_sync(0xffffffffu, attn, k);
        float bx = __shfl_sync(0xffffffffu, rx, k);
        float by = __shfl_sync(0xffffffffu, ry, k);
        float bz = __shfl_sync(0xffffffffu, rz, k);
        int   r  = __shfl_sync(0xffffffffu, row, k);
        const float* fr = feat + (size_t)r*D;
        #pragma unroll
        for (int i = 0; i < 4; ++i) {
            int d = lane + 32*i;
            float h = fmaf(bx, w0[i], fmaf(by, w1[i], fmaf(bz, w2[i], b1r[i])));
            h = fmaxf(h, 0.f);
            hb[i] = fmaf(a, h, hb[i]);
            fb[i] = fmaf(a, fr[d], fb[i]);
        }
    }
    #pragma unroll
    for (int i = 0; i < 4; ++i) {
        int d = lane + 32*i;
        g_hbar[(size_t)p*D + d] = hb[i];
        g_fbar[(size_t)p*D + d] = fb[i];
    }
}

// ---------------- out = feat + gamma*(fbar@Wvo + hbar@Wf + cvec) ----------------
__global__ void k_out(const float* __restrict__ feat, const float* __restrict__ gamma,
                      float* __restrict__ out) {
    __shared__ float As[16][132];
    __shared__ float Ws[16][132];
    int m0 = blockIdx.x*128;
    int tx = threadIdx.x & 15, ty = threadIdx.x >> 4;
    float acc[8][8];
    #pragma unroll
    for (int i = 0; i < 8; ++i)
        #pragma unroll
        for (int j = 0; j < 8; ++j) acc[i][j] = 0.f;

    for (int ph = 0; ph < 2; ++ph) {
        const float* A = ph ? g_hbar : g_fbar;
        const float* W = ph ? g_wf   : g_wvo;
        for (int kc = 0; kc < D; kc += 16) {
            __syncthreads();
            { int c = threadIdx.x & 3, r = threadIdx.x >> 2;
              #pragma unroll
              for (int rr = 0; rr < 2; ++rr) {
                  int mm = r + rr*64;
                  float4 v = *(const float4*)&A[(size_t)(m0+mm)*D + kc + c*4];
                  As[c*4+0][mm] = v.x; As[c*4+1][mm] = v.y;
                  As[c*4+2][mm] = v.z; As[c*4+3][mm] = v.w;
              }
            }
            { int k = threadIdx.x >> 5, c4 = threadIdx.x & 31;
              #pragma unroll
              for (int kk = 0; kk < 2; ++kk) {
                  float4 v = *(const float4*)&W[(size_t)(kc + k + kk*8)*D + c4*4];
                  Ws[k + kk*8][c4*4+0] = v.x; Ws[k + kk*8][c4*4+1] = v.y;
                  Ws[k + kk*8][c4*4+2] = v.z; Ws[k + kk*8][c4*4+3] = v.w;
              }
            }
            __syncthreads();
            #pragma unroll
            for (int k = 0; k < 16; ++k) {
                float a[8], bb[8];
                #pragma unroll
                for (int i = 0; i < 8; ++i) a[i]  = As[k][ty*8 + i];
                #pragma unroll
                for (int j = 0; j < 8; ++j) bb[j] = Ws[k][tx*8 + j];
                #pragma unroll
                for (int i = 0; i < 8; ++i)
                    #pragma unroll
                    for (int j = 0; j < 8; ++j) acc[i][j] = fmaf(a[i], bb[j], acc[i][j]);
            }
        }
    }
    float g = *gamma;
    float cv[8];
    #pragma unroll
    for (int j = 0; j < 8; ++j) cv[j] = g_cvec[tx*8 + j];
    #pragma unroll
    for (int i = 0; i < 8; ++i) {
        int m = m0 + ty*8 + i;
        float4 f0 = *(const float4*)&feat[(size_t)m*D + tx*8];
        float4 f1 = *(const float4*)&feat[(size_t)m*D + tx*8 + 4];
        float o0 = f0.x + g*(acc[i][0] + cv[0]);
        float o1 = f0.y + g*(acc[i][1] + cv[1]);
        float o2 = f0.z + g*(acc[i][2] + cv[2]);
        float o3 = f0.w + g*(acc[i][3] + cv[3]);
        float o4 = f1.x + g*(acc[i][4] + cv[4]);
        float o5 = f1.y + g*(acc[i][5] + cv[5]);
        float o6 = f1.z + g*(acc[i][6] + cv[6]);
        float o7 = f1.w + g*(acc[i][7] + cv[7]);
        *(float4*)&out[(size_t)m*D + tx*8]     = make_float4(o0, o1, o2, o3);
        *(float4*)&out[(size_t)m*D + tx*8 + 4] = make_float4(o4, o5, o6, o7);
    }
}

// ---------------- launch ----------------
extern "C" void kernel_launch(void* const* d_in, const int* in_sizes, int n_in,
                              void* d_out, int out_size) {
    const float* xyz  = (const float*)d_in[0];
    const float* feat = (const float*)d_in[1];
    // d_in[2]=Wq, d_in[3]=bq, d_in[5]=bk : mathematically cancel in softmax, unused
    const float* Wk   = (const float*)d_in[4];
    const float* Wv   = (const float*)d_in[6];
    const float* bv   = (const float*)d_in[7];
    const float* Wp1  = (const float*)d_in[8];
    const float* bp1  = (const float*)d_in[9];
    const float* Wp2  = (const float*)d_in[10];
    const float* bp2  = (const float*)d_in[11];
    const float* Wo   = (const float*)d_in[12];
    const float* bo   = (const float*)d_in[13];
    const float* gmm  = (const float*)d_in[14];
    float* out = (float*)d_out;

    k_zero<<<NB*NCELLS/256, 256>>>();
    k_weights<<<1, 128>>>(Wk, Wp2, bp2, Wo, bo, bv);
    k_wfused<<<128, 256>>>(Wp2, Wv, Wo);
    k_prep<<<BN/8, 256>>>(xyz, feat);
    k_bbox<<<dim3(32, NB), 256>>>(xyz);
    k_hist<<<BN/256, 256>>>(xyz);
    k_scan<<<NB, 1024>>>();
    k_scatter<<<BN/256, 256>>>(xyz);
    k_taabb<<<NB*NTILES/8, 256>>>();
    k_knn<<<BN/32, 128>>>();
    k_fuse<<<BN/4, 128>>>(xyz, Wp1, bp1, feat);
    k_out<<<BN/128, 256>>>(feat, gmm, out);
}

// round 17
// speedup vs baseline: 1.5527x; 1.0215x over previous
#include <cuda_runtime.h>
#include <math.h>
#include <math_constants.h>

#define NB   4
#define NPTS 8192
#define BN   (NB*NPTS)   // 32768
#define D    128
#define KNN  16
#define G    16
#define NCELLS (G*G*G)   // 4096 cells per batch
#define TPW  32          // tile slots per warp (own tile == the 32 queries)
#define NTILES (NPTS/TPW) // 256 tiles per batch
#define NW   4           // warps per query group

// ---------------- scratch (static device allocations) ----------------
__device__ float4   g_xyzw[BN];        // (-2x,-2y,-2z, |x|^2) per point (orig order)
__device__ float4   g_spts[BN];        // same, sorted by (batch, morton cell)
__device__ int      g_sidx[BN];        // sorted slot -> original local idx
__device__ unsigned g_cnt[NB*NCELLS];  // histogram
__device__ unsigned g_off[NB*NCELLS];  // cell start offsets (batch-local)
__device__ unsigned g_cur[NB*NCELLS];  // scatter cursors
__device__ unsigned g_bblo[NB*3], g_bbhi[NB*3];  // encoded bbox
__device__ float4   g_tlo[NB*NTILES];  // per-tile AABB min (xyz)
__device__ float4   g_thi[NB*NTILES];  // per-tile AABB max (xyz)
__device__ float  g_ksum[BN];          // feat . rowsum(Wk)
__device__ int    g_idx[BN*KNN];       // knn indices (within batch)
__device__ float  g_hbar[BN*D];        // sum_k attn_k * h_k
__device__ float  g_fbar[BN*D];        // sum_k attn_k * feat_k
__device__ float  g_wkrs[D];           // rowsum over out-dim of Wk
__device__ float  g_wp2rs[D];          // rowsum over out-dim of Wp2
__device__ float  g_cvec[D];           // (bv + bp2) @ Wo + bo
__device__ float  g_wf[D*D];           // Wp2 @ Wo
__device__ float  g_wvo[D*D];          // Wv @ Wo

// ---------------- helpers ----------------
__device__ __forceinline__ unsigned fenc(float f) {
    unsigned u = __float_as_uint(f);
    return (u & 0x80000000u) ? ~u : (u | 0x80000000u);
}
__device__ __forceinline__ float fdec(unsigned u) {
    return (u & 0x80000000u) ? __uint_as_float(u ^ 0x80000000u) : __uint_as_float(~u);
}
__device__ __forceinline__ unsigned msp4(unsigned x) {
    return (x & 1u) | ((x & 2u) << 2) | ((x & 4u) << 4) | ((x & 8u) << 6);
}
__device__ __forceinline__ unsigned morton3(int cx, int cy, int cz) {
    return msp4((unsigned)cx) | (msp4((unsigned)cy) << 1) | (msp4((unsigned)cz) << 2);
}
__device__ __forceinline__ int cell1(float x, float lo, float inv) {
    int v = (int)((x - lo) * inv);
    return v < 0 ? 0 : (v > G-1 ? G-1 : v);
}

// ---------------- init ----------------
__global__ void k_zero() {   // 64 blocks x 256
    int i = blockIdx.x*256 + threadIdx.x;
    g_cnt[i] = 0;
    if (i < NB*3) { g_bblo[i] = 0xFFFFFFFFu; g_bbhi[i] = 0u; }
}

// ---------------- weight prep ----------------
__global__ void k_weights(const float* __restrict__ Wk, const float* __restrict__ Wp2,
                          const float* __restrict__ bp2, const float* __restrict__ Wo,
                          const float* __restrict__ bo, const float* __restrict__ bv) {
    int i = threadIdx.x;
    float a = 0.f, b = 0.f, c = bo[i];
    for (int j = 0; j < D; ++j) { a += Wk[i*D + j]; b += Wp2[i*D + j]; }
    for (int k = 0; k < D; ++k) c = fmaf(bp2[k] + bv[k], Wo[k*D + i], c);
    g_wkrs[i] = a; g_wp2rs[i] = b; g_cvec[i] = c;
}

// Wf = Wp2 @ Wo  and  Wvo = Wv @ Wo   (128 blocks x 256)
__global__ void k_wfused(const float* __restrict__ Wp2, const float* __restrict__ Wv,
                         const float* __restrict__ Wo) {
    int d = threadIdx.x & (D-1);
    int r = blockIdx.x*2 + (threadIdx.x >> 7);   // 0..255
    const float* A = (r < D) ? Wp2 : Wv;
    float* O = (r < D) ? g_wf : g_wvo;
    int i = r & (D-1);
    float a = 0.f;
    for (int k = 0; k < D; ++k) a = fmaf(A[i*D + k], Wo[k*D + d], a);
    O[i*D + d] = a;
}

// ---------------- per-point prep: xyzw + ksum + batch bbox ----------------
__global__ void k_prep(const float* __restrict__ xyz, const float* __restrict__ feat) {
    __shared__ unsigned slo[3], shi[3];
    if (threadIdx.x < 3) { slo[threadIdx.x] = 0xFFFFFFFFu; shi[threadIdx.x] = 0u; }
    __syncthreads();
    int warp = threadIdx.x >> 5, lane = threadIdx.x & 31;
    int p = blockIdx.x*8 + warp;
    const float* fr = feat + (size_t)p*D;
    float acc = 0.f;
    #pragma unroll
    for (int i = 0; i < 4; ++i) {
        int d = lane + 32*i;
        acc = fmaf(fr[d], g_wkrs[d], acc);
    }
    #pragma unroll
    for (int off = 16; off; off >>= 1) acc += __shfl_xor_sync(0xffffffffu, acc, off);
    if (lane == 0) {
        g_ksum[p] = acc;
        float x = xyz[3*p], y = xyz[3*p+1], z = xyz[3*p+2];
        g_xyzw[p] = make_float4(-2.f*x, -2.f*y, -2.f*z, x*x + y*y + z*z);
        unsigned ex = fenc(x), ey = fenc(y), ez = fenc(z);
        atomicMin(&slo[0], ex); atomicMax(&shi[0], ex);
        atomicMin(&slo[1], ey); atomicMax(&shi[1], ey);
        atomicMin(&slo[2], ez); atomicMax(&shi[2], ez);
    }
    __syncthreads();
    if (threadIdx.x < 3) {
        int b = (blockIdx.x*8) >> 13;   // all 8 points of a block share a batch
        atomicMin(&g_bblo[b*3 + threadIdx.x], slo[threadIdx.x]);
        atomicMax(&g_bbhi[b*3 + threadIdx.x], shi[threadIdx.x]);
    }
}

// ---------------- histogram over morton cells ----------------
__global__ void k_hist(const float* __restrict__ xyz) {
    int i = blockIdx.x*256 + threadIdx.x;
    int b = i >> 13;
    float lox = fdec(g_bblo[b*3]),   loy = fdec(g_bblo[b*3+1]), loz = fdec(g_bblo[b*3+2]);
    float ivx = (float)G/(fdec(g_bbhi[b*3])   - lox + 1e-4f);
    float ivy = (float)G/(fdec(g_bbhi[b*3+1]) - loy + 1e-4f);
    float ivz = (float)G/(fdec(g_bbhi[b*3+2]) - loz + 1e-4f);
    float x = xyz[3*i], y = xyz[3*i+1], z = xyz[3*i+2];
    unsigned m = morton3(cell1(x,lox,ivx), cell1(y,loy,ivy), cell1(z,loz,ivz));
    atomicAdd(&g_cnt[b*NCELLS + m], 1u);
}

// ---------------- exclusive scan per batch (4096 cells) ----------------
__global__ void k_scan() {   // grid NB, block 1024
    int b = blockIdx.x;
    int tid = threadIdx.x, lane = tid & 31, wid = tid >> 5;
    __shared__ unsigned ws[32];
    __shared__ unsigned carry_s;
    if (tid == 0) carry_s = 0;
    __syncthreads();
    for (int it = 0; it < NCELLS/1024; ++it) {
        unsigned carry = carry_s;
        int i = b*NCELLS + it*1024 + tid;
        unsigned v = g_cnt[i];
        unsigned s = v;
        #pragma unroll
        for (int off = 1; off < 32; off <<= 1) {
            unsigned n = __shfl_up_sync(0xffffffffu, s, off);
            if (lane >= off) s += n;
        }
        if (lane == 31) ws[wid] = s;
        __syncthreads();
        if (wid == 0) {
            unsigned t = ws[lane];
            #pragma unroll
            for (int off = 1; off < 32; off <<= 1) {
                unsigned n = __shfl_up_sync(0xffffffffu, t, off);
                if (lane >= off) t += n;
            }
            ws[lane] = t;
        }
        __syncthreads();
        unsigned excl = s - v + (wid ? ws[wid-1] : 0u) + carry;
        g_off[i] = excl; g_cur[i] = excl;
        __syncthreads();
        if (tid == 1023) carry_s = excl + v;
        __syncthreads();
    }
}

// ---------------- scatter into morton-sorted order ----------------
__global__ void k_scatter(const float* __restrict__ xyz) {
    int i = blockIdx.x*256 + threadIdx.x;
    int b = i >> 13;
    float lox = fdec(g_bblo[b*3]),   loy = fdec(g_bblo[b*3+1]), loz = fdec(g_bblo[b*3+2]);
    float ivx = (float)G/(fdec(g_bbhi[b*3])   - lox + 1e-4f);
    float ivy = (float)G/(fdec(g_bbhi[b*3+1]) - loy + 1e-4f);
    float ivz = (float)G/(fdec(g_bbhi[b*3+2]) - loz + 1e-4f);
    float x = xyz[3*i], y = xyz[3*i+1], z = xyz[3*i+2];
    unsigned m = morton3(cell1(x,lox,ivx), cell1(y,loy,ivy), cell1(z,loz,ivz));
    unsigned pos = atomicAdd(&g_cur[b*NCELLS + m], 1u);
    int slot = b*NPTS + (int)pos;
    g_spts[slot] = g_xyzw[i];
    g_sidx[slot] = i & (NPTS-1);
}

// ---------------- per-tile AABB (exact, from points) ----------------
__global__ void k_taabb() {   // NB*NTILES/8 blocks x 256 (8 warps)
    int w = threadIdx.x >> 5, lane = threadIdx.x & 31;
    int tile = blockIdx.x*8 + w;
    float xmn = CUDART_INF_F, ymn = CUDART_INF_F, zmn = CUDART_INF_F;
    float xmx = -CUDART_INF_F, ymx = -CUDART_INF_F, zmx = -CUDART_INF_F;
    #pragma unroll
    for (int i = 0; i < TPW/32; ++i) {
        float4 c = g_spts[tile*TPW + lane + i*32];
        float x = -0.5f*c.x, y = -0.5f*c.y, z = -0.5f*c.z;
        xmn = fminf(xmn, x); xmx = fmaxf(xmx, x);
        ymn = fminf(ymn, y); ymx = fmaxf(ymx, y);
        zmn = fminf(zmn, z); zmx = fmaxf(zmx, z);
    }
    #pragma unroll
    for (int off = 16; off; off >>= 1) {
        xmn = fminf(xmn, __shfl_xor_sync(0xffffffffu, xmn, off));
        xmx = fmaxf(xmx, __shfl_xor_sync(0xffffffffu, xmx, off));
        ymn = fminf(ymn, __shfl_xor_sync(0xffffffffu, ymn, off));
        ymx = fmaxf(ymx, __shfl_xor_sync(0xffffffffu, ymx, off));
        zmn = fminf(zmn, __shfl_xor_sync(0xffffffffu, zmn, off));
        zmx = fmaxf(zmx, __shfl_xor_sync(0xffffffffu, zmx, off));
    }
    if (lane == 0) {
        g_tlo[tile] = make_float4(xmn, ymn, zmn, 0.f);
        g_thi[tile] = make_float4(xmx, ymx, zmx, 0.f);
    }
}

// ---------------- kNN: AABB-pruned center-out tile scan, 4 warps/group ----------------
__global__ void __launch_bounds__(128) k_knn() {
    __shared__ float4 tile_s[NW][TPW];     // 2KB
    __shared__ float  sth[NW][32];         // per-(warp,query) 16th-dist^2
    __shared__ float  md[KNN*NW*32];       // merge keys
    __shared__ int    mi[KNN*NW*32];       // merge slot ids

    int w = threadIdx.x >> 5, lane = threadIdx.x & 31;
    int qslot0 = blockIdx.x*32;            // 32 consecutive morton-sorted queries
    int b = qslot0 >> 13, bbase = b*NPTS;
    int ql = qslot0 & (NPTS-1);
    int slot = qslot0 + lane;
    float4 qc = g_spts[slot];
    float qx = -0.5f*qc.x, qy = -0.5f*qc.y, qz = -0.5f*qc.z, qw = qc.w;

    volatile float* sv = &sth[0][0];
    sth[w][lane] = CUDART_INF_F;

    float kk[KNN]; int ii[KNN];
    #pragma unroll
    for (int s = 0; s < KNN; ++s) { kk[s] = CUDART_INF_F; ii[s] = 0; }
    float pkey = 0.f; int psl = 0; bool pval = false;

#define KNN_FLUSH() do {                                              \
        float ck = pkey; int ci = psl;                                \
        _Pragma("unroll")                                             \
        for (int s = 0; s < KNN; ++s) {                               \
            bool sw = ck < kk[s];                                     \
            float tk = kk[s]; int ti = ii[s];                         \
            kk[s] = sw ? ck : tk;  ii[s] = sw ? ci : ti;              \
            ck = sw ? tk : ck;     ci = sw ? ti : ci;                 \
        }                                                             \
    } while (0)

#define SCAN_TILE(T0, CAP) do {                                       \
        __syncwarp();                                                 \
        _Pragma("unroll")                                             \
        for (int i_ = 0; i_ < TPW/32; ++i_)                           \
            tile_s[w][lane + i_*32] = g_spts[bbase + (T0) + lane + i_*32]; \
        __syncwarp();                                                 \
        float thr = fminf(kk[KNN-1], (CAP));                          \
        _Pragma("unroll 8")                                           \
        for (int j_ = 0; j_ < TPW; ++j_) {                            \
            float4 c = tile_s[w][j_];                                 \
            float key = fmaf(c.x, qx, fmaf(c.y, qy, fmaf(c.z, qz, c.w))); \
            bool hit = key < thr;                                     \
            if (__any_sync(0xffffffffu, hit && pval)) {               \
                if (pval) { KNN_FLUSH(); thr = fminf(kk[KNN-1], (CAP)); } \
                pval = false;                                         \
            }                                                         \
            if (hit) { pkey = key; psl = (T0) + j_; pval = true; }    \
        }                                                             \
        if (__any_sync(0xffffffffu, pval)) {                          \
            if (pval) KNN_FLUSH();                                    \
            pval = false;                                             \
        }                                                             \
        sth[w][lane] = kk[KNN-1] + qw;                                \
    } while (0)

    __syncthreads();
    int tq = ql / TPW;                      // own tile (== the 32 queries)
    if (w == 0) SCAN_TILE(tq*TPW, CUDART_INF_F);   // warm-start
    __syncthreads();

    // center-out tile order: t = tq+1, tq-1, tq+2, tq-2, ... dealt round-robin
    // across the 4 warps. Near (likely-surviving) tiles are scanned first,
    // tightening the shared bound before far tiles are prune-tested.
    for (int j = w; j < 2*(NTILES-1); j += NW) {
        int off = (j >> 1) + 1;
        int t = (j & 1) ? tq - off : tq + off;
        if ((unsigned)t >= NTILES) continue;
        float d2s = fminf(fminf(sv[lane], sv[32+lane]), fminf(sv[64+lane], sv[96+lane]));
        d2s = fminf(d2s, kk[KNN-1] + qw);
        float4 blo = g_tlo[b*NTILES + t];
        float4 bhi = g_thi[b*NTILES + t];
        float dx = fmaxf(fmaxf(blo.x - qx, qx - bhi.x), 0.f);
        float dy = fmaxf(fmaxf(blo.y - qy, qy - bhi.y), 0.f);
        float dz = fmaxf(fmaxf(blo.z - qz, qz - bhi.z), 0.f);
        float cd2 = fmaf(dx, dx, fmaf(dy, dy, dz*dz));
        if (__all_sync(0xffffffffu, cd2 >= d2s + 1e-4f)) continue;  // margin > key rounding
        SCAN_TILE(t*TPW, d2s - qw);
    }
#undef SCAN_TILE
#undef KNN_FLUSH

    // ---- 4-way merge of sorted 16-lists (disjoint tiles -> no duplicates) ----
    #pragma unroll
    for (int s = 0; s < KNN; ++s) {
        md[s*(NW*32) + w*32 + lane] = kk[s];
        mi[s*(NW*32) + w*32 + lane] = ii[s];
    }
    __syncthreads();
    if (w == 0) {
        int p0 = 0, p1 = 0, p2 = 0, p3 = 0;
        int oq = g_sidx[slot];
        int* op = g_idx + (size_t)(bbase + oq)*KNN;
        #pragma unroll
        for (int s = 0; s < KNN; ++s) {
            float h0 = md[p0*128 +  0 + lane];
            float h1 = md[p1*128 + 32 + lane];
            float h2 = md[p2*128 + 64 + lane];
            float h3 = md[p3*128 + 96 + lane];
            float best = h0; int bw = 0;
            if (h1 < best) { best = h1; bw = 1; }
            if (h2 < best) { best = h2; bw = 2; }
            if (h3 < best) { best = h3; bw = 3; }
            int pj = (bw == 0) ? p0 : (bw == 1) ? p1 : (bw == 2) ? p2 : p3;
            int sl = mi[pj*128 + bw*32 + lane];
            op[s] = g_sidx[bbase + sl];
            if (bw == 0) ++p0; else if (bw == 1) ++p1; else if (bw == 2) ++p2; else ++p3;
        }
    }
}

// ---------------- fused attention (warp per point): fbar instead of vbar ----------------
__global__ void k_fuse(const float* __restrict__ xyz, const float* __restrict__ Wp1,
                       const float* __restrict__ bp1, const float* __restrict__ feat) {
    __shared__ float sw0[D], sw1[D], sw2[D], sb1[D], srs[D];
    int tid = threadIdx.x;
    sw0[tid] = Wp1[tid]; sw1[tid] = Wp1[D + tid]; sw2[tid] = Wp1[2*D + tid];
    sb1[tid] = bp1[tid]; srs[tid] = g_wp2rs[tid];
    __syncthreads();

    int warp = tid >> 5, lane = tid & 31;
    int p = blockIdx.x*4 + warp;
    int bbase = p & ~(NPTS-1);

    float w0[4], w1[4], w2[4], b1r[4], rs[4];
    #pragma unroll
    for (int i = 0; i < 4; ++i) {
        int d = lane + 32*i;
        w0[i] = sw0[d]; w1[i] = sw1[d]; w2[i] = sw2[d]; b1r[i] = sb1[d]; rs[i] = srs[d];
    }

    float rx = 0.f, ry = 0.f, rz = 0.f, ks = 0.f; int row = 0;
    if (lane < KNN) {
        int nb = g_idx[(size_t)p*KNN + lane];
        row = bbase + nb;
        float qx = xyz[3*p], qy = xyz[3*p+1], qz = xyz[3*p+2];
        rx = qx - xyz[3*row]; ry = qy - xyz[3*row+1]; rz = qz - xyz[3*row+2];
        ks = g_ksum[row];
    }

    // pass 1: attention logits  score_k = h_k . rowsum(Wp2) - ksum_k
    float mysc = -CUDART_INF_F;
    #pragma unroll
    for (int k = 0; k < KNN; ++k) {
        float bx = __shfl_sync(0xffffffffu, rx, k);
        float by = __shfl_sync(0xffffffffu, ry, k);
        float bz = __shfl_sync(0xffffffffu, rz, k);
        float part = 0.f;
        #pragma unroll
        for (int i = 0; i < 4; ++i) {
            float h = fmaf(bx, w0[i], fmaf(by, w1[i], fmaf(bz, w2[i], b1r[i])));
            h = fmaxf(h, 0.f);
            part = fmaf(h, rs[i], part);
        }
        #pragma unroll
        for (int off = 16; off; off >>= 1) part += __shfl_xor_sync(0xffffffffu, part, off);
        if (lane == k) mysc = part - ks;
    }
    // softmax over the 16 neighbor lanes
    float mx = mysc;
    #pragma unroll
    for (int off = 16; off; off >>= 1) mx = fmaxf(mx, __shfl_xor_sync(0xffffffffu, mx, off));
    float e = (lane < KNN) ? __expf(mysc - mx) : 0.f;
    float ssum = e;
    #pragma unroll
    for (int off = 16; off; off >>= 1) ssum += __shfl_xor_sync(0xffffffffu, ssum, off);
    float attn = e / ssum;

    // pass 2: hbar = sum attn*h, fbar = sum attn*feat
    float hb[4] = {0,0,0,0}, fb[4] = {0,0,0,0};
    #pragma unroll
    for (int k = 0; k < KNN; ++k) {
        float a  = __shfl_sync(0xffffffffu, attn, k);
        float bx = __shfl_sync(0xffffffffu, rx, k);
        float by = __shfl_sync(0xffffffffu, ry, k);
        float bz = __shfl_sync(0xffffffffu, rz, k);
        int   r  = __shfl_sync(0xffffffffu, row, k);
        const float* fr = feat + (size_t)r*D;
        #pragma unroll
        for (int i = 0; i < 4; ++i) {
            int d = lane + 32*i;
            float h = fmaf(bx, w0[i], fmaf(by, w1[i], fmaf(bz, w2[i], b1r[i])));
            h = fmaxf(h, 0.f);
            hb[i] = fmaf(a, h, hb[i]);
            fb[i] = fmaf(a, fr[d], fb[i]);
        }
    }
    #pragma unroll
    for (int i = 0; i < 4; ++i) {
        int d = lane + 32*i;
        g_hbar[(size_t)p*D + d] = hb[i];
        g_fbar[(size_t)p*D + d] = fb[i];
    }
}

// ---------------- out = feat + gamma*(fbar@Wvo + hbar@Wf + cvec) ----------------
__global__ void k_out(const float* __restrict__ feat, const float* __restrict__ gamma,
                      float* __restrict__ out) {
    __shared__ float As[16][132];
    __shared__ float Ws[16][132];
    int m0 = blockIdx.x*128;
    int tx = threadIdx.x & 15, ty = threadIdx.x >> 4;
    float acc[8][8];
    #pragma unroll
    for (int i = 0; i < 8; ++i)
        #pragma unroll
        for (int j = 0; j < 8; ++j) acc[i][j] = 0.f;

    for (int ph = 0; ph < 2; ++ph) {
        const float* A = ph ? g_hbar : g_fbar;
        const float* W = ph ? g_wf   : g_wvo;
        for (int kc = 0; kc < D; kc += 16) {
            __syncthreads();
            { int c = threadIdx.x & 3, r = threadIdx.x >> 2;
              #pragma unroll
              for (int rr = 0; rr < 2; ++rr) {
                  int mm = r + rr*64;
                  float4 v = *(const float4*)&A[(size_t)(m0+mm)*D + kc + c*4];
                  As[c*4+0][mm] = v.x; As[c*4+1][mm] = v.y;
                  As[c*4+2][mm] = v.z; As[c*4+3][mm] = v.w;
              }
            }
            { int k = threadIdx.x >> 5, c4 = threadIdx.x & 31;
              #pragma unroll
              for (int kk = 0; kk < 2; ++kk) {
                  float4 v = *(const float4*)&W[(size_t)(kc + k + kk*8)*D + c4*4];
                  Ws[k + kk*8][c4*4+0] = v.x; Ws[k + kk*8][c4*4+1] = v.y;
                  Ws[k + kk*8][c4*4+2] = v.z; Ws[k + kk*8][c4*4+3] = v.w;
              }
            }
            __syncthreads();
            #pragma unroll
            for (int k = 0; k < 16; ++k) {
                float a[8], bb[8];
                #pragma unroll
                for (int i = 0; i < 8; ++i) a[i]  = As[k][ty*8 + i];
                #pragma unroll
                for (int j = 0; j < 8; ++j) bb[j] = Ws[k][tx*8 + j];
                #pragma unroll
                for (int i = 0; i < 8; ++i)
                    #pragma unroll
                    for (int j = 0; j < 8; ++j) acc[i][j] = fmaf(a[i], bb[j], acc[i][j]);
            }
        }
    }
    float g = *gamma;
    float cv[8];
    #pragma unroll
    for (int j = 0; j < 8; ++j) cv[j] = g_cvec[tx*8 + j];
    #pragma unroll
    for (int i = 0; i < 8; ++i) {
        int m = m0 + ty*8 + i;
        float4 f0 = *(const float4*)&feat[(size_t)m*D + tx*8];
        float4 f1 = *(const float4*)&feat[(size_t)m*D + tx*8 + 4];
        float o0 = f0.x + g*(acc[i][0] + cv[0]);
        float o1 = f0.y + g*(acc[i][1] + cv[1]);
        float o2 = f0.z + g*(acc[i][2] + cv[2]);
        float o3 = f0.w + g*(acc[i][3] + cv[3]);
        float o4 = f1.x + g*(acc[i][4] + cv[4]);
        float o5 = f1.y + g*(acc[i][5] + cv[5]);
        float o6 = f1.z + g*(acc[i][6] + cv[6]);
        float o7 = f1.w + g*(acc[i][7] + cv[7]);
        *(float4*)&out[(size_t)m*D + tx*8]     = make_float4(o0, o1, o2, o3);
        *(float4*)&out[(size_t)m*D + tx*8 + 4] = make_float4(o4, o5, o6, o7);
    }
}

// ---------------- launch ----------------
extern "C" void kernel_launch(void* const* d_in, const int* in_sizes, int n_in,
                              void* d_out, int out_size) {
    const float* xyz  = (const float*)d_in[0];
    const float* feat = (const float*)d_in[1];
    // d_in[2]=Wq, d_in[3]=bq, d_in[5]=bk : mathematically cancel in softmax, unused
    const float* Wk   = (const float*)d_in[4];
    const float* Wv   = (const float*)d_in[6];
    const float* bv   = (const float*)d_in[7];
    const float* Wp1  = (const float*)d_in[8];
    const float* bp1  = (const float*)d_in[9];
    const float* Wp2  = (const float*)d_in[10];
    const float* bp2  = (const float*)d_in[11];
    const float* Wo   = (const float*)d_in[12];
    const float* bo   = (const float*)d_in[13];
    const float* gmm  = (const float*)d_in[14];
    float* out = (float*)d_out;

    k_zero<<<NB*NCELLS/256, 256>>>();
    k_weights<<<1, 128>>>(Wk, Wp2, bp2, Wo, bo, bv);
    k_wfused<<<128, 256>>>(Wp2, Wv, Wo);
    k_prep<<<BN/8, 256>>>(xyz, feat);
    k_hist<<<BN/256, 256>>>(xyz);
    k_scan<<<NB, 1024>>>();
    k_scatter<<<BN/256, 256>>>(xyz);
    k_taabb<<<NB*NTILES/8, 256>>>();
    k_knn<<<BN/32, 128>>>();
    k_fuse<<<BN/4, 128>>>(xyz, Wp1, bp1, feat);
    k_out<<<BN/128, 256>>>(feat, gmm, out);
}